// round 1
// baseline (speedup 1.0000x reference)
#include <cuda_runtime.h>
#include <math.h>

#define NN 5000
#define NFEAT 512
#define NHID 64
#define NHEADS 8
#define NCLASS 40
#define LRALPHA 0.2f
#define MAXDEG 128

// ---------------- device scratch (no allocations allowed) ----------------
__device__ float d_Wh [NN * NHEADS * NHID];   // [N, 512]  layer-1 Wh, col = h*64+o
__device__ float d_h1 [NN * NHEADS * NHID];   // [N, 512]  concat'd elu(head outputs)
__device__ float d_Wh2[NN * NHID];            // [N, 64]
__device__ float d_f1 [NHEADS * NN];
__device__ float d_f2 [NHEADS * NN];
__device__ float d_g1 [NN];
__device__ float d_g2 [NN];
__device__ int   d_nbr[NN * MAXDEG];
__device__ int   d_cnt[NN];

__device__ __forceinline__ float leaky(float t) { return t > 0.f ? t : LRALPHA * t; }
__device__ __forceinline__ float elu1(float t)  { return t > 0.f ? t : expf(t) - 1.f; }

// ---------------- K0: adjacency -> neighbor lists (one 100MB scan) -------
__global__ void gat_build_csr(const float* __restrict__ adj) {
    int n = blockIdx.x;
    __shared__ int cnt;
    if (threadIdx.x == 0) cnt = 0;
    __syncthreads();
    const float4* row = reinterpret_cast<const float4*>(adj + (size_t)n * NN);
    for (int i = threadIdx.x; i < NN / 4; i += blockDim.x) {
        float4 v = row[i];
        int c = i * 4;
        if (v.x != 0.f) { int p = atomicAdd(&cnt, 1); if (p < MAXDEG) d_nbr[n * MAXDEG + p] = c;     }
        if (v.y != 0.f) { int p = atomicAdd(&cnt, 1); if (p < MAXDEG) d_nbr[n * MAXDEG + p] = c + 1; }
        if (v.z != 0.f) { int p = atomicAdd(&cnt, 1); if (p < MAXDEG) d_nbr[n * MAXDEG + p] = c + 2; }
        if (v.w != 0.f) { int p = atomicAdd(&cnt, 1); if (p < MAXDEG) d_nbr[n * MAXDEG + p] = c + 3; }
    }
    __syncthreads();
    if (threadIdx.x == 0) d_cnt[n] = min(cnt, MAXDEG);
}

// ---------------- K1/K4: tiled fp32 GEMM, 64x64 tile, 256 thr, 4x4/thr ---
// C[m, colOff + j] = sum_k A[m,k] * B[k,j], B per-blockIdx.y slab is contiguous [K,64]
__global__ void gat_gemm64(const float* __restrict__ A, const float* __restrict__ B0,
                           float* __restrict__ C, int M, int K, int ldc, long bHeadStride) {
    const int BM = 64, BN = 64, BK = 16;
    int m0 = blockIdx.x * BM;
    const float* B = B0 + (size_t)blockIdx.y * bHeadStride;
    int colOff = blockIdx.y * BN;

    __shared__ float As[BK][BM + 4];
    __shared__ float Bs[BK][BN];

    int tid = threadIdx.x;
    int tx = tid & 15, ty = tid >> 4;
    float acc[4][4] = {};

    for (int k0 = 0; k0 < K; k0 += BK) {
        #pragma unroll
        for (int i = 0; i < 4; i++) {
            int idx = tid + i * 256;
            int m = idx >> 4, k = idx & 15;
            float v = (m0 + m < M) ? A[(size_t)(m0 + m) * K + k0 + k] : 0.f;
            As[k][m] = v;
        }
        reinterpret_cast<float4*>(Bs)[tid] =
            reinterpret_cast<const float4*>(B + (size_t)k0 * BN)[tid];
        __syncthreads();
        #pragma unroll
        for (int k = 0; k < BK; k++) {
            float4 a = *reinterpret_cast<const float4*>(&As[k][ty * 4]);
            float4 b = *reinterpret_cast<const float4*>(&Bs[k][tx * 4]);
            acc[0][0] += a.x * b.x; acc[0][1] += a.x * b.y; acc[0][2] += a.x * b.z; acc[0][3] += a.x * b.w;
            acc[1][0] += a.y * b.x; acc[1][1] += a.y * b.y; acc[1][2] += a.y * b.z; acc[1][3] += a.y * b.w;
            acc[2][0] += a.z * b.x; acc[2][1] += a.z * b.y; acc[2][2] += a.z * b.z; acc[2][3] += a.z * b.w;
            acc[3][0] += a.w * b.x; acc[3][1] += a.w * b.y; acc[3][2] += a.w * b.z; acc[3][3] += a.w * b.w;
        }
        __syncthreads();
    }
    #pragma unroll
    for (int i = 0; i < 4; i++) {
        int m = m0 + ty * 4 + i;
        if (m < M) {
            float4 v = make_float4(acc[i][0], acc[i][1], acc[i][2], acc[i][3]);
            *reinterpret_cast<float4*>(C + (size_t)m * ldc + colOff + tx * 4) = v;
        }
    }
}

// ---------------- K2: f1/f2 per (head, node) ------------------------------
__global__ void gat_f12(const float* __restrict__ a_h) {
    int n = blockIdx.x;
    int w = threadIdx.x >> 5, lane = threadIdx.x & 31;
    const float* p = d_Wh + (size_t)n * 512 + w * 64;
    float v0 = p[lane], v1 = p[lane + 32];
    float s1 = v0 * a_h[w * 128 + lane]      + v1 * a_h[w * 128 + lane + 32];
    float s2 = v0 * a_h[w * 128 + 64 + lane] + v1 * a_h[w * 128 + 96 + lane];
    #pragma unroll
    for (int off = 16; off; off >>= 1) {
        s1 += __shfl_xor_sync(0xffffffffu, s1, off);
        s2 += __shfl_xor_sync(0xffffffffu, s2, off);
    }
    if (lane == 0) { d_f1[w * NN + n] = s1; d_f2[w * NN + n] = s2; }
}

// ---------------- K3: layer-1 sparse attention + aggregation + elu --------
__global__ void gat_agg1() {
    int n = blockIdx.x;
    __shared__ int   s_idx[MAXDEG];
    __shared__ float s_f2[NHEADS][MAXDEG];
    __shared__ float s_w [NHEADS][MAXDEG];
    int tid = threadIdx.x;
    int deg = d_cnt[n];

    for (int j = tid; j < deg; j += 256) s_idx[j] = d_nbr[n * MAXDEG + j];
    __syncthreads();
    for (int t = tid; t < deg * NHEADS; t += 256) {
        int h = t / deg, j = t - h * deg;
        s_f2[h][j] = d_f2[h * NN + s_idx[j]];
    }
    __syncthreads();

    int w = tid >> 5, lane = tid & 31;
    float f1v = d_f1[w * NN + n];

    float mx = -1e30f;
    for (int j = lane; j < deg; j += 32) mx = fmaxf(mx, leaky(f1v + s_f2[w][j]));
    #pragma unroll
    for (int off = 16; off; off >>= 1) mx = fmaxf(mx, __shfl_xor_sync(0xffffffffu, mx, off));

    float sum = 0.f;
    for (int j = lane; j < deg; j += 32) {
        float e = expf(leaky(f1v + s_f2[w][j]) - mx);
        s_w[w][j] = e;
        sum += e;
    }
    #pragma unroll
    for (int off = 16; off; off >>= 1) sum += __shfl_xor_sync(0xffffffffu, sum, off);
    __syncwarp();

    float acc0 = 0.f, acc1 = 0.f;
    for (int j = 0; j < deg; j++) {
        float wj = s_w[w][j];
        const float* p = d_Wh + (size_t)s_idx[j] * 512 + w * 64;
        acc0 += wj * p[lane];
        acc1 += wj * p[lane + 32];
    }
    float inv = 1.f / sum;
    d_h1[(size_t)n * 512 + w * 64 + lane]      = elu1(acc0 * inv);
    d_h1[(size_t)n * 512 + w * 64 + lane + 32] = elu1(acc1 * inv);
}

// ---------------- K5: g1/g2 ------------------------------------------------
__global__ void gat_g12(const float* __restrict__ a_o) {
    int n = blockIdx.x * 8 + (threadIdx.x >> 5);
    if (n >= NN) return;
    int lane = threadIdx.x & 31;
    float v0 = d_Wh2[n * 64 + lane], v1 = d_Wh2[n * 64 + lane + 32];
    float s1 = v0 * a_o[lane]      + v1 * a_o[lane + 32];
    float s2 = v0 * a_o[64 + lane] + v1 * a_o[96 + lane];
    #pragma unroll
    for (int off = 16; off; off >>= 1) {
        s1 += __shfl_xor_sync(0xffffffffu, s1, off);
        s2 += __shfl_xor_sync(0xffffffffu, s2, off);
    }
    if (lane == 0) { d_g1[n] = s1; d_g2[n] = s2; }
}

// ---------------- K6: layer-2 attention + aggregation + MLP head ----------
__global__ void gat_agg2_mlp(const float* __restrict__ fc1_w, const float* __restrict__ fc1_b,
                             const float* __restrict__ fc2_w, const float* __restrict__ fc2_b,
                             float* __restrict__ out) {
    int n = blockIdx.x;
    __shared__ int   s_idx[MAXDEG];
    __shared__ float s_g2[MAXDEG];
    __shared__ float s_w [MAXDEG];
    __shared__ float s_sum;
    __shared__ float s_part[4][64];
    __shared__ float s_h2[64];
    __shared__ float s_h3[200];
    __shared__ float s_p2[5][40];
    int tid = threadIdx.x;
    int deg = d_cnt[n];

    for (int j = tid; j < deg; j += 256) {
        int c = d_nbr[n * MAXDEG + j];
        s_idx[j] = c;
        s_g2[j]  = d_g2[c];
    }
    __syncthreads();

    if (tid < 32) {
        float g1n = d_g1[n];
        float mx = -1e30f;
        for (int j = tid; j < deg; j += 32) mx = fmaxf(mx, leaky(g1n + s_g2[j]));
        #pragma unroll
        for (int off = 16; off; off >>= 1) mx = fmaxf(mx, __shfl_xor_sync(0xffffffffu, mx, off));
        float sum = 0.f;
        for (int j = tid; j < deg; j += 32) {
            float e = expf(leaky(g1n + s_g2[j]) - mx);
            s_w[j] = e;
            sum += e;
        }
        #pragma unroll
        for (int off = 16; off; off >>= 1) sum += __shfl_xor_sync(0xffffffffu, sum, off);
        if (tid == 0) s_sum = sum;
    }
    __syncthreads();

    // h2 = (att2 @ Wh2)[n]  — split deg over 4 partial accumulators
    {
        int o = tid & 63, part = tid >> 6;
        float acc = 0.f;
        for (int j = part; j < deg; j += 4)
            acc += s_w[j] * d_Wh2[(size_t)s_idx[j] * 64 + o];
        s_part[part][o] = acc;
    }
    __syncthreads();
    if (tid < 64)
        s_h2[tid] = (s_part[0][tid] + s_part[1][tid] + s_part[2][tid] + s_part[3][tid]) / s_sum;
    __syncthreads();

    // h3 = elu(h2 @ fc1_w + fc1_b)
    if (tid < 200) {
        float acc = fc1_b[tid];
        #pragma unroll 8
        for (int f = 0; f < 64; f++) acc += s_h2[f] * fc1_w[f * 200 + tid];
        s_h3[tid] = elu1(acc);
    }
    __syncthreads();

    // out = h3 @ fc2_w + fc2_b  — split k=200 over 5 partials
    if (tid < 200) {
        int c = tid % 40, part = tid / 40;
        float acc = 0.f;
        for (int k = part; k < 200; k += 5) acc += s_h3[k] * fc2_w[k * 40 + c];
        s_p2[part][c] = acc;
    }
    __syncthreads();
    if (tid < 40)
        out[(size_t)n * 40 + tid] =
            s_p2[0][tid] + s_p2[1][tid] + s_p2[2][tid] + s_p2[3][tid] + s_p2[4][tid] + fc2_b[tid];
}

// ---------------- launch ----------------------------------------------------
extern "C" void kernel_launch(void* const* d_in, const int* in_sizes, int n_in,
                              void* d_out, int out_size) {
    const float* x     = (const float*)d_in[0];
    const float* adj   = (const float*)d_in[1];
    const float* W_h   = (const float*)d_in[2];
    const float* a_h   = (const float*)d_in[3];
    const float* W_o   = (const float*)d_in[4];
    const float* a_o   = (const float*)d_in[5];
    const float* fc1_w = (const float*)d_in[6];
    const float* fc1_b = (const float*)d_in[7];
    const float* fc2_w = (const float*)d_in[8];
    const float* fc2_b = (const float*)d_in[9];
    float* out = (float*)d_out;

    void *pWh, *pH1, *pWh2;
    cudaGetSymbolAddress(&pWh,  d_Wh);
    cudaGetSymbolAddress(&pH1,  d_h1);
    cudaGetSymbolAddress(&pWh2, d_Wh2);

    int mblocks = (NN + 63) / 64;

    gat_build_csr<<<NN, 256>>>(adj);
    gat_gemm64<<<dim3(mblocks, NHEADS), 256>>>(x, W_h, (float*)pWh,
                                               NN, NFEAT, 512, (long)NFEAT * NHID);
    gat_f12<<<NN, 256>>>(a_h);
    gat_agg1<<<NN, 256>>>();
    gat_gemm64<<<dim3(mblocks, 1), 256>>>((const float*)pH1, W_o, (float*)pWh2,
                                          NN, NHEADS * NHID, 64, 0L);
    gat_g12<<<(NN + 7) / 8, 256>>>(a_o);
    gat_agg2_mlp<<<NN, 256>>>(fc1_w, fc1_b, fc2_w, fc2_b, out);
}

// round 3
// speedup vs baseline: 1.2639x; 1.2639x over previous
#include <cuda_runtime.h>
#include <math.h>
#include <cstdint>

#define NN 5000
#define NFEAT 512
#define NHID 64
#define NHEADS 8
#define NCLASS 40
#define LRALPHA 0.2f
#define MAXDEG 128

// ---------------- device scratch (no allocations allowed) ----------------
__device__ float d_Wh [NN * NHEADS * NHID];   // [N, 512]
__device__ float d_h1 [NN * NHEADS * NHID];   // [N, 512]
__device__ float d_Wh2[NN * NHID];            // [N, 64]
__device__ float d_Bt1[512 * 512];            // packed W_h^T  [n=h*64+o][k], tf32
__device__ float d_Bt2[64 * 512];             // packed W_o^T  [n][k], tf32
__device__ float d_f1 [NHEADS * NN];
__device__ float d_f2 [NHEADS * NN];
__device__ float d_g1 [NN];
__device__ float d_g2 [NN];
__device__ int   d_nbr[NN * MAXDEG];
__device__ int   d_cnt[NN];

__device__ __forceinline__ float leaky(float t) { return t > 0.f ? t : LRALPHA * t; }
__device__ __forceinline__ float elu1(float t)  { return t > 0.f ? t : expf(t) - 1.f; }
__device__ __forceinline__ uint32_t f2tf32(float f) {
    uint32_t u;
    asm("cvt.rna.tf32.f32 %0, %1;" : "=r"(u) : "f"(f));
    return u;
}
__device__ __forceinline__ void mma_tf32(float& c0, float& c1, float& c2, float& c3,
                                         uint32_t a0, uint32_t a1, uint32_t a2, uint32_t a3,
                                         uint32_t b0, uint32_t b1) {
    asm volatile("mma.sync.aligned.m16n8k8.row.col.f32.tf32.tf32.f32 "
                 "{%0,%1,%2,%3}, {%4,%5,%6,%7}, {%8,%9}, {%0,%1,%2,%3};"
                 : "+f"(c0), "+f"(c1), "+f"(c2), "+f"(c3)
                 : "r"(a0), "r"(a1), "r"(a2), "r"(a3), "r"(b0), "r"(b1));
}

// ---------------- K0: adjacency -> neighbor lists --------------------------
__global__ void gat_build_csr(const float* __restrict__ adj) {
    int n = blockIdx.x;
    __shared__ int cnt;
    if (threadIdx.x == 0) cnt = 0;
    __syncthreads();
    const float4* row = reinterpret_cast<const float4*>(adj + (size_t)n * NN);
    for (int i = threadIdx.x; i < NN / 4; i += blockDim.x) {
        float4 v = row[i];
        int c = i * 4;
        if (v.x != 0.f) { int p = atomicAdd(&cnt, 1); if (p < MAXDEG) d_nbr[n * MAXDEG + p] = c;     }
        if (v.y != 0.f) { int p = atomicAdd(&cnt, 1); if (p < MAXDEG) d_nbr[n * MAXDEG + p] = c + 1; }
        if (v.z != 0.f) { int p = atomicAdd(&cnt, 1); if (p < MAXDEG) d_nbr[n * MAXDEG + p] = c + 2; }
        if (v.w != 0.f) { int p = atomicAdd(&cnt, 1); if (p < MAXDEG) d_nbr[n * MAXDEG + p] = c + 3; }
    }
    __syncthreads();
    if (threadIdx.x == 0) d_cnt[n] = min(cnt, MAXDEG);
}

// ---------------- pack weights into [N][K] tf32 ----------------------------
__global__ void gat_pack_Bt1(const float* __restrict__ W_h) {
    int idx = blockIdx.x * 256 + threadIdx.x;        // 512*512
    int n = idx >> 9, k = idx & 511;
    int h = n >> 6, o = n & 63;
    d_Bt1[idx] = __uint_as_float(f2tf32(W_h[h * NFEAT * NHID + k * NHID + o]));
}
__global__ void gat_pack_Bt2(const float* __restrict__ W_o) {
    int idx = blockIdx.x * 256 + threadIdx.x;        // 64*512
    int n = idx >> 9, k = idx & 511;
    d_Bt2[idx] = __uint_as_float(f2tf32(W_o[k * NHID + n]));
}

// ---------------- tf32 HMMA GEMM: C[m, n0+j] = sum_k A[m,k]*Bt[n0+j,k] -----
// CTA tile 128 x NT, k-tile 32. 256 threads.
// NT=128: 4x2 warps, warp tile 32x64.  NT=64: 8x1 warps, warp tile 16x64.
#define SPAD 36
template<int NT>
__global__ void __launch_bounds__(256) gat_mma_gemm(
        const float* __restrict__ A, const float* __restrict__ Bt,
        float* __restrict__ C, int M, int ldc) {
    constexpr int WARPS_M = (NT == 128) ? 4 : 8;
    constexpr int WM = 128 / WARPS_M;      // 32 or 16
    constexpr int MT = WM / 16;            // 2 or 1

    __shared__ uint32_t As[128][SPAD];
    __shared__ uint32_t Bs[NT][SPAD];

    int tid = threadIdx.x, w = tid >> 5, l = tid & 31;
    int m0 = blockIdx.x * 128, n0 = blockIdx.y * NT;
    int wm = w % WARPS_M, wn = w / WARPS_M;
    int mbase = wm * WM, nbase = wn * 64;

    float acc[MT][8][4];
    #pragma unroll
    for (int i = 0; i < MT; i++)
        #pragma unroll
        for (int j = 0; j < 8; j++)
            #pragma unroll
            for (int q = 0; q < 4; q++) acc[i][j][q] = 0.f;

    int lq = l >> 2, lr = l & 3;

    for (int kt = 0; kt < 16; kt++) {
        int k0 = kt * 32;
        // A tile: 128 rows x 32 cols, tf32-converted
        #pragma unroll
        for (int i = 0; i < 4; i++) {
            int f = tid + i * 256;
            int r = f >> 3, c4 = (f & 7) * 4;
            float4 v = make_float4(0.f, 0.f, 0.f, 0.f);
            int m = m0 + r;
            if (m < M) v = *reinterpret_cast<const float4*>(A + (size_t)m * 512 + k0 + c4);
            As[r][c4]     = f2tf32(v.x);
            As[r][c4 + 1] = f2tf32(v.y);
            As[r][c4 + 2] = f2tf32(v.z);
            As[r][c4 + 3] = f2tf32(v.w);
        }
        // B tile: NT rows x 32 cols (already tf32)
        #pragma unroll
        for (int i = 0; i < NT / 32; i++) {
            int f = tid + i * 256;
            int r = f >> 3, c4 = (f & 7) * 4;
            float4 v = *reinterpret_cast<const float4*>(Bt + (size_t)(n0 + r) * 512 + k0 + c4);
            Bs[r][c4]     = __float_as_uint(v.x);
            Bs[r][c4 + 1] = __float_as_uint(v.y);
            Bs[r][c4 + 2] = __float_as_uint(v.z);
            Bs[r][c4 + 3] = __float_as_uint(v.w);
        }
        __syncthreads();

        #pragma unroll
        for (int ks = 0; ks < 4; ks++) {
            int kc = ks * 8 + lr;
            uint32_t af[MT][4];
            #pragma unroll
            for (int mt = 0; mt < MT; mt++) {
                int rb = mbase + mt * 16 + lq;
                af[mt][0] = As[rb][kc];
                af[mt][1] = As[rb + 8][kc];
                af[mt][2] = As[rb][kc + 4];
                af[mt][3] = As[rb + 8][kc + 4];
            }
            #pragma unroll
            for (int nt = 0; nt < 8; nt++) {
                int nb = nbase + nt * 8 + lq;
                uint32_t b0 = Bs[nb][kc];
                uint32_t b1 = Bs[nb][kc + 4];
                #pragma unroll
                for (int mt = 0; mt < MT; mt++)
                    mma_tf32(acc[mt][nt][0], acc[mt][nt][1], acc[mt][nt][2], acc[mt][nt][3],
                             af[mt][0], af[mt][1], af[mt][2], af[mt][3], b0, b1);
            }
        }
        __syncthreads();
    }

    // epilogue
    #pragma unroll
    for (int mt = 0; mt < MT; mt++) {
        int r0 = m0 + mbase + mt * 16 + lq;
        int r1 = r0 + 8;
        #pragma unroll
        for (int nt = 0; nt < 8; nt++) {
            int c = n0 + nbase + nt * 8 + lr * 2;
            if (r0 < M)
                *reinterpret_cast<float2*>(C + (size_t)r0 * ldc + c) =
                    make_float2(acc[mt][nt][0], acc[mt][nt][1]);
            if (r1 < M)
                *reinterpret_cast<float2*>(C + (size_t)r1 * ldc + c) =
                    make_float2(acc[mt][nt][2], acc[mt][nt][3]);
        }
    }
}

// ---------------- K2: f1/f2 per (head, node) ------------------------------
__global__ void gat_f12(const float* __restrict__ a_h) {
    int n = blockIdx.x;
    int w = threadIdx.x >> 5, lane = threadIdx.x & 31;
    const float* p = d_Wh + (size_t)n * 512 + w * 64;
    float v0 = p[lane], v1 = p[lane + 32];
    float s1 = v0 * a_h[w * 128 + lane]      + v1 * a_h[w * 128 + lane + 32];
    float s2 = v0 * a_h[w * 128 + 64 + lane] + v1 * a_h[w * 128 + 96 + lane];
    #pragma unroll
    for (int off = 16; off; off >>= 1) {
        s1 += __shfl_xor_sync(0xffffffffu, s1, off);
        s2 += __shfl_xor_sync(0xffffffffu, s2, off);
    }
    if (lane == 0) { d_f1[w * NN + n] = s1; d_f2[w * NN + n] = s2; }
}

// ---------------- K3: layer-1 sparse attention + aggregation + elu --------
__global__ void gat_agg1() {
    int n = blockIdx.x;
    __shared__ int   s_idx[MAXDEG];
    __shared__ float s_f2[NHEADS][MAXDEG];
    __shared__ float s_w [NHEADS][MAXDEG];
    int tid = threadIdx.x;
    int deg = d_cnt[n];

    for (int j = tid; j < deg; j += 256) s_idx[j] = d_nbr[n * MAXDEG + j];
    __syncthreads();
    for (int t = tid; t < deg * NHEADS; t += 256) {
        int h = t / deg, j = t - h * deg;
        s_f2[h][j] = d_f2[h * NN + s_idx[j]];
    }
    __syncthreads();

    int w = tid >> 5, lane = tid & 31;
    float f1v = d_f1[w * NN + n];

    float mx = -1e30f;
    for (int j = lane; j < deg; j += 32) mx = fmaxf(mx, leaky(f1v + s_f2[w][j]));
    #pragma unroll
    for (int off = 16; off; off >>= 1) mx = fmaxf(mx, __shfl_xor_sync(0xffffffffu, mx, off));

    float sum = 0.f;
    for (int j = lane; j < deg; j += 32) {
        float e = expf(leaky(f1v + s_f2[w][j]) - mx);
        s_w[w][j] = e;
        sum += e;
    }
    #pragma unroll
    for (int off = 16; off; off >>= 1) sum += __shfl_xor_sync(0xffffffffu, sum, off);
    __syncwarp();

    float accx = 0.f, accy = 0.f;
    for (int j = 0; j < deg; j++) {
        float wj = s_w[w][j];
        float2 v = reinterpret_cast<const float2*>(d_Wh + (size_t)s_idx[j] * 512 + w * 64)[lane];
        accx += wj * v.x;
        accy += wj * v.y;
    }
    float inv = 1.f / sum;
    float2 o = make_float2(elu1(accx * inv), elu1(accy * inv));
    reinterpret_cast<float2*>(d_h1 + (size_t)n * 512 + w * 64)[lane] = o;
}

// ---------------- K5: g1/g2 ------------------------------------------------
__global__ void gat_g12(const float* __restrict__ a_o) {
    int n = blockIdx.x * 8 + (threadIdx.x >> 5);
    if (n >= NN) return;
    int lane = threadIdx.x & 31;
    float v0 = d_Wh2[n * 64 + lane], v1 = d_Wh2[n * 64 + lane + 32];
    float s1 = v0 * a_o[lane]      + v1 * a_o[lane + 32];
    float s2 = v0 * a_o[64 + lane] + v1 * a_o[96 + lane];
    #pragma unroll
    for (int off = 16; off; off >>= 1) {
        s1 += __shfl_xor_sync(0xffffffffu, s1, off);
        s2 += __shfl_xor_sync(0xffffffffu, s2, off);
    }
    if (lane == 0) { d_g1[n] = s1; d_g2[n] = s2; }
}

// ---------------- K6: layer-2 attention + aggregation + MLP head ----------
__global__ void gat_agg2_mlp(const float* __restrict__ fc1_w, const float* __restrict__ fc1_b,
                             const float* __restrict__ fc2_w, const float* __restrict__ fc2_b,
                             float* __restrict__ out) {
    int n = blockIdx.x;
    __shared__ int   s_idx[MAXDEG];
    __shared__ float s_g2[MAXDEG];
    __shared__ float s_w [MAXDEG];
    __shared__ float s_sum;
    __shared__ float s_part[4][64];
    __shared__ float s_h2[64];
    __shared__ float s_h3[200];
    __shared__ float s_p2[5][40];
    int tid = threadIdx.x;
    int deg = d_cnt[n];

    for (int j = tid; j < deg; j += 256) {
        int c = d_nbr[n * MAXDEG + j];
        s_idx[j] = c;
        s_g2[j]  = d_g2[c];
    }
    __syncthreads();

    if (tid < 32) {
        float g1n = d_g1[n];
        float mx = -1e30f;
        for (int j = tid; j < deg; j += 32) mx = fmaxf(mx, leaky(g1n + s_g2[j]));
        #pragma unroll
        for (int off = 16; off; off >>= 1) mx = fmaxf(mx, __shfl_xor_sync(0xffffffffu, mx, off));
        float sum = 0.f;
        for (int j = tid; j < deg; j += 32) {
            float e = expf(leaky(g1n + s_g2[j]) - mx);
            s_w[j] = e;
            sum += e;
        }
        #pragma unroll
        for (int off = 16; off; off >>= 1) sum += __shfl_xor_sync(0xffffffffu, sum, off);
        if (tid == 0) s_sum = sum;
    }
    __syncthreads();

    {
        int o = tid & 63, part = tid >> 6;
        float acc = 0.f;
        for (int j = part; j < deg; j += 4)
            acc += s_w[j] * d_Wh2[(size_t)s_idx[j] * 64 + o];
        s_part[part][o] = acc;
    }
    __syncthreads();
    if (tid < 64)
        s_h2[tid] = (s_part[0][tid] + s_part[1][tid] + s_part[2][tid] + s_part[3][tid]) / s_sum;
    __syncthreads();

    if (tid < 200) {
        float acc = fc1_b[tid];
        #pragma unroll 8
        for (int f = 0; f < 64; f++) acc += s_h2[f] * fc1_w[f * 200 + tid];
        s_h3[tid] = elu1(acc);
    }
    __syncthreads();

    if (tid < 200) {
        int c = tid % 40, part = tid / 40;
        float acc = 0.f;
        for (int k = part; k < 200; k += 5) acc += s_h3[k] * fc2_w[k * 40 + c];
        s_p2[part][c] = acc;
    }
    __syncthreads();
    if (tid < 40)
        out[(size_t)n * 40 + tid] =
            s_p2[0][tid] + s_p2[1][tid] + s_p2[2][tid] + s_p2[3][tid] + s_p2[4][tid] + fc2_b[tid];
}

// ---------------- launch ----------------------------------------------------
extern "C" void kernel_launch(void* const* d_in, const int* in_sizes, int n_in,
                              void* d_out, int out_size) {
    const float* x     = (const float*)d_in[0];
    const float* adj   = (const float*)d_in[1];
    const float* W_h   = (const float*)d_in[2];
    const float* a_h   = (const float*)d_in[3];
    const float* W_o   = (const float*)d_in[4];
    const float* a_o   = (const float*)d_in[5];
    const float* fc1_w = (const float*)d_in[6];
    const float* fc1_b = (const float*)d_in[7];
    const float* fc2_w = (const float*)d_in[8];
    const float* fc2_b = (const float*)d_in[9];
    float* out = (float*)d_out;

    void *pWh, *pH1, *pWh2, *pBt1, *pBt2;
    cudaGetSymbolAddress(&pWh,  d_Wh);
    cudaGetSymbolAddress(&pH1,  d_h1);
    cudaGetSymbolAddress(&pWh2, d_Wh2);
    cudaGetSymbolAddress(&pBt1, d_Bt1);
    cudaGetSymbolAddress(&pBt2, d_Bt2);

    const int MB = (NN + 127) / 128;   // 40

    gat_build_csr<<<NN, 256>>>(adj);
    gat_pack_Bt1<<<512 * 512 / 256, 256>>>(W_h);
    gat_mma_gemm<128><<<dim3(MB, 4), 256>>>(x, (const float*)pBt1, (float*)pWh, NN, 512);
    gat_f12<<<NN, 256>>>(a_h);
    gat_agg1<<<NN, 256>>>();
    gat_pack_Bt2<<<64 * 512 / 256, 256>>>(W_o);
    gat_mma_gemm<64><<<dim3(MB, 1), 256>>>((const float*)pH1, (const float*)pBt2, (float*)pWh2, NN, 64);
    gat_g12<<<(NN + 7) / 8, 256>>>(a_o);
    gat_agg2_mlp<<<NN, 256>>>(fc1_w, fc1_b, fc2_w, fc2_b, out);
}

// round 4
// speedup vs baseline: 1.2982x; 1.0272x over previous
#include <cuda_runtime.h>
#include <math.h>
#include <cstdint>

#define NN 5000
#define NFEAT 512
#define NHID 64
#define NHEADS 8
#define NCLASS 40
#define LRALPHA 0.2f
#define MAXDEG 128

// ---------------- device scratch (no allocations allowed) ----------------
__device__ float d_Wh [NN * NHEADS * NHID];   // [N, 512]
__device__ float d_h1 [NN * NHEADS * NHID];   // [N, 512]
__device__ float d_Wh2[NN * NHID];            // [N, 64]
__device__ float d_Bt1[512 * 512];            // packed W_h^T  [n=h*64+o][k], tf32
__device__ float d_Bt2[64 * 512];             // packed W_o^T  [n][k], tf32
__device__ float d_f1 [NHEADS * NN];
__device__ float d_f2 [NHEADS * NN];
__device__ float d_g1 [NN];
__device__ float d_g2 [NN];
__device__ int   d_nbr[NN * MAXDEG];
__device__ int   d_cnt[NN];

__device__ __forceinline__ float leaky(float t) { return t > 0.f ? t : LRALPHA * t; }
__device__ __forceinline__ float elu1(float t)  { return t > 0.f ? t : expf(t) - 1.f; }
__device__ __forceinline__ uint32_t f2tf32(float f) {
    uint32_t u;
    asm("cvt.rna.tf32.f32 %0, %1;" : "=r"(u) : "f"(f));
    return u;
}
__device__ __forceinline__ void mma_tf32(float& c0, float& c1, float& c2, float& c3,
                                         uint32_t a0, uint32_t a1, uint32_t a2, uint32_t a3,
                                         uint32_t b0, uint32_t b1) {
    asm volatile("mma.sync.aligned.m16n8k8.row.col.f32.tf32.tf32.f32 "
                 "{%0,%1,%2,%3}, {%4,%5,%6,%7}, {%8,%9}, {%0,%1,%2,%3};"
                 : "+f"(c0), "+f"(c1), "+f"(c2), "+f"(c3)
                 : "r"(a0), "r"(a1), "r"(a2), "r"(a3), "r"(b0), "r"(b1));
}

// ---------------- K0: adjacency -> neighbor lists --------------------------
__global__ void gat_build_csr(const float* __restrict__ adj) {
    int n = blockIdx.x;
    __shared__ int cnt;
    if (threadIdx.x == 0) cnt = 0;
    __syncthreads();
    const float4* row = reinterpret_cast<const float4*>(adj + (size_t)n * NN);
    for (int i = threadIdx.x; i < NN / 4; i += blockDim.x) {
        float4 v = row[i];
        int c = i * 4;
        if (v.x != 0.f) { int p = atomicAdd(&cnt, 1); if (p < MAXDEG) d_nbr[n * MAXDEG + p] = c;     }
        if (v.y != 0.f) { int p = atomicAdd(&cnt, 1); if (p < MAXDEG) d_nbr[n * MAXDEG + p] = c + 1; }
        if (v.z != 0.f) { int p = atomicAdd(&cnt, 1); if (p < MAXDEG) d_nbr[n * MAXDEG + p] = c + 2; }
        if (v.w != 0.f) { int p = atomicAdd(&cnt, 1); if (p < MAXDEG) d_nbr[n * MAXDEG + p] = c + 3; }
    }
    __syncthreads();
    if (threadIdx.x == 0) d_cnt[n] = min(cnt, MAXDEG);
}

// ---------------- pack weights into [N][K] tf32 ----------------------------
__global__ void gat_pack_Bt1(const float* __restrict__ W_h) {
    int idx = blockIdx.x * 256 + threadIdx.x;        // 512*512
    int n = idx >> 9, k = idx & 511;
    int h = n >> 6, o = n & 63;
    d_Bt1[idx] = __uint_as_float(f2tf32(W_h[h * NFEAT * NHID + k * NHID + o]));
}
__global__ void gat_pack_Bt2(const float* __restrict__ W_o) {
    int idx = blockIdx.x * 256 + threadIdx.x;        // 64*512
    int n = idx >> 9, k = idx & 511;
    d_Bt2[idx] = __uint_as_float(f2tf32(W_o[k * NHID + n]));
}

// ---------------- tf32 HMMA GEMM + fused attention-vector dots -------------
// C[m, n0+j] = sum_k A[m,k]*Bt[n0+j,k];  also f1/f2 = C-slice . av halves.
// NT=128: 4x2 warps, head = 2*by+wn, av=a_h, out f1/f2 at head*NN.
// NT=64 : 8x1 warps, av=a_o (128 floats), out g1/g2 (offset 0).
#define SPAD 36
template<int NT>
__global__ void __launch_bounds__(256) gat_mma_gemm(
        const float* __restrict__ A, const float* __restrict__ Bt,
        float* __restrict__ C, int M, int ldc,
        const float* __restrict__ av, float* __restrict__ f1o, float* __restrict__ f2o) {
    constexpr int WARPS_M = (NT == 128) ? 4 : 8;
    constexpr int WM = 128 / WARPS_M;      // 32 or 16
    constexpr int MT = WM / 16;            // 2 or 1
    constexpr int ASZ = (NT == 128) ? 256 : 128;

    __shared__ uint32_t As[128][SPAD];
    __shared__ uint32_t Bs[NT][SPAD];
    __shared__ float    s_a[ASZ];

    int tid = threadIdx.x, w = tid >> 5, l = tid & 31;
    int m0 = blockIdx.x * 128, n0 = blockIdx.y * NT;
    int wm = w % WARPS_M, wn = w / WARPS_M;
    int mbase = wm * WM, nbase = wn * 64;

    if (tid < ASZ) s_a[tid] = av[(NT == 128 ? blockIdx.y * 256 : 0) + tid];

    float acc[MT][8][4];
    #pragma unroll
    for (int i = 0; i < MT; i++)
        #pragma unroll
        for (int j = 0; j < 8; j++)
            #pragma unroll
            for (int q = 0; q < 4; q++) acc[i][j][q] = 0.f;

    int lq = l >> 2, lr = l & 3;

    for (int kt = 0; kt < 16; kt++) {
        int k0 = kt * 32;
        #pragma unroll
        for (int i = 0; i < 4; i++) {
            int f = tid + i * 256;
            int r = f >> 3, c4 = (f & 7) * 4;
            float4 v = make_float4(0.f, 0.f, 0.f, 0.f);
            int m = m0 + r;
            if (m < M) v = *reinterpret_cast<const float4*>(A + (size_t)m * 512 + k0 + c4);
            As[r][c4]     = f2tf32(v.x);
            As[r][c4 + 1] = f2tf32(v.y);
            As[r][c4 + 2] = f2tf32(v.z);
            As[r][c4 + 3] = f2tf32(v.w);
        }
        #pragma unroll
        for (int i = 0; i < NT / 32; i++) {
            int f = tid + i * 256;
            int r = f >> 3, c4 = (f & 7) * 4;
            float4 v = *reinterpret_cast<const float4*>(Bt + (size_t)(n0 + r) * 512 + k0 + c4);
            Bs[r][c4]     = __float_as_uint(v.x);
            Bs[r][c4 + 1] = __float_as_uint(v.y);
            Bs[r][c4 + 2] = __float_as_uint(v.z);
            Bs[r][c4 + 3] = __float_as_uint(v.w);
        }
        __syncthreads();

        #pragma unroll
        for (int ks = 0; ks < 4; ks++) {
            int kc = ks * 8 + lr;
            uint32_t af[MT][4];
            #pragma unroll
            for (int mt = 0; mt < MT; mt++) {
                int rb = mbase + mt * 16 + lq;
                af[mt][0] = As[rb][kc];
                af[mt][1] = As[rb + 8][kc];
                af[mt][2] = As[rb][kc + 4];
                af[mt][3] = As[rb + 8][kc + 4];
            }
            #pragma unroll
            for (int nt = 0; nt < 8; nt++) {
                int nb = nbase + nt * 8 + lq;
                uint32_t b0 = Bs[nb][kc];
                uint32_t b1 = Bs[nb][kc + 4];
                #pragma unroll
                for (int mt = 0; mt < MT; mt++)
                    mma_tf32(acc[mt][nt][0], acc[mt][nt][1], acc[mt][nt][2], acc[mt][nt][3],
                             af[mt][0], af[mt][1], af[mt][2], af[mt][3], b0, b1);
            }
        }
        __syncthreads();
    }

    // epilogue: store C
    #pragma unroll
    for (int mt = 0; mt < MT; mt++) {
        int r0 = m0 + mbase + mt * 16 + lq;
        int r1 = r0 + 8;
        #pragma unroll
        for (int nt = 0; nt < 8; nt++) {
            int c = n0 + nbase + nt * 8 + lr * 2;
            if (r0 < M)
                *reinterpret_cast<float2*>(C + (size_t)r0 * ldc + c) =
                    make_float2(acc[mt][nt][0], acc[mt][nt][1]);
            if (r1 < M)
                *reinterpret_cast<float2*>(C + (size_t)r1 * ldc + c) =
                    make_float2(acc[mt][nt][2], acc[mt][nt][3]);
        }
    }

    // fused attention-vector dot products (f1/f2 or g1/g2)
    {
        const float* va = s_a + ((NT == 128) ? wn * 128 : 0);
        float p1[MT][2] = {}, p2[MT][2] = {};
        #pragma unroll
        for (int nt = 0; nt < 8; nt++) {
            int o = nt * 8 + lr * 2;
            float a1x = va[o], a1y = va[o + 1];
            float a2x = va[64 + o], a2y = va[64 + o + 1];
            #pragma unroll
            for (int mt = 0; mt < MT; mt++) {
                p1[mt][0] += acc[mt][nt][0] * a1x + acc[mt][nt][1] * a1y;
                p2[mt][0] += acc[mt][nt][0] * a2x + acc[mt][nt][1] * a2y;
                p1[mt][1] += acc[mt][nt][2] * a1x + acc[mt][nt][3] * a1y;
                p2[mt][1] += acc[mt][nt][2] * a2x + acc[mt][nt][3] * a2y;
            }
        }
        #pragma unroll
        for (int mt = 0; mt < MT; mt++)
            #pragma unroll
            for (int rr = 0; rr < 2; rr++) {
                p1[mt][rr] += __shfl_xor_sync(0xffffffffu, p1[mt][rr], 1);
                p1[mt][rr] += __shfl_xor_sync(0xffffffffu, p1[mt][rr], 2);
                p2[mt][rr] += __shfl_xor_sync(0xffffffffu, p2[mt][rr], 1);
                p2[mt][rr] += __shfl_xor_sync(0xffffffffu, p2[mt][rr], 2);
            }
        if (lr == 0) {
            size_t hoff = (NT == 128) ? (size_t)(blockIdx.y * 2 + wn) * NN : 0;
            #pragma unroll
            for (int mt = 0; mt < MT; mt++) {
                int r0 = m0 + mbase + mt * 16 + lq;
                int r1 = r0 + 8;
                if (r0 < M) { f1o[hoff + r0] = p1[mt][0]; f2o[hoff + r0] = p2[mt][0]; }
                if (r1 < M) { f1o[hoff + r1] = p1[mt][1]; f2o[hoff + r1] = p2[mt][1]; }
            }
        }
    }
}

// ---------------- K3: layer-1 sparse attention + aggregation + elu --------
__global__ void gat_agg1() {
    int n = blockIdx.x;
    __shared__ int   s_idx[MAXDEG];
    __shared__ float s_f2[NHEADS][MAXDEG];
    __shared__ float s_w [NHEADS][MAXDEG];
    int tid = threadIdx.x;
    int deg = d_cnt[n];

    for (int j = tid; j < deg; j += 256) s_idx[j] = d_nbr[n * MAXDEG + j];
    __syncthreads();
    for (int t = tid; t < deg * NHEADS; t += 256) {
        int h = t / deg, j = t - h * deg;
        s_f2[h][j] = d_f2[h * NN + s_idx[j]];
    }
    __syncthreads();

    int w = tid >> 5, lane = tid & 31;
    float f1v = d_f1[w * NN + n];

    float mx = -1e30f;
    for (int j = lane; j < deg; j += 32) mx = fmaxf(mx, leaky(f1v + s_f2[w][j]));
    #pragma unroll
    for (int off = 16; off; off >>= 1) mx = fmaxf(mx, __shfl_xor_sync(0xffffffffu, mx, off));

    float sum = 0.f;
    for (int j = lane; j < deg; j += 32) {
        float e = expf(leaky(f1v + s_f2[w][j]) - mx);
        s_w[w][j] = e;
        sum += e;
    }
    #pragma unroll
    for (int off = 16; off; off >>= 1) sum += __shfl_xor_sync(0xffffffffu, sum, off);
    __syncwarp();

    float accx = 0.f, accy = 0.f;
    for (int j = 0; j < deg; j++) {
        float wj = s_w[w][j];
        float2 v = reinterpret_cast<const float2*>(d_Wh + (size_t)s_idx[j] * 512 + w * 64)[lane];
        accx += wj * v.x;
        accy += wj * v.y;
    }
    float inv = 1.f / sum;
    float2 o = make_float2(elu1(accx * inv), elu1(accy * inv));
    reinterpret_cast<float2*>(d_h1 + (size_t)n * 512 + w * 64)[lane] = o;
}

// ---------------- K6: layer-2 attention + aggregation + MLP head ----------
__global__ void gat_agg2_mlp(const float* __restrict__ fc1_w, const float* __restrict__ fc1_b,
                             const float* __restrict__ fc2_w, const float* __restrict__ fc2_b,
                             float* __restrict__ out) {
    int n = blockIdx.x;
    __shared__ int   s_idx[MAXDEG];
    __shared__ float s_g2[MAXDEG];
    __shared__ float s_w [MAXDEG];
    __shared__ float s_sum;
    __shared__ float s_part[4][64];
    __shared__ float s_h2[64];
    __shared__ float s_h3[200];
    __shared__ float s_p2[5][40];
    int tid = threadIdx.x;
    int deg = d_cnt[n];

    for (int j = tid; j < deg; j += 256) {
        int c = d_nbr[n * MAXDEG + j];
        s_idx[j] = c;
        s_g2[j]  = d_g2[c];
    }
    __syncthreads();

    if (tid < 32) {
        float g1n = d_g1[n];
        float mx = -1e30f;
        for (int j = tid; j < deg; j += 32) mx = fmaxf(mx, leaky(g1n + s_g2[j]));
        #pragma unroll
        for (int off = 16; off; off >>= 1) mx = fmaxf(mx, __shfl_xor_sync(0xffffffffu, mx, off));
        float sum = 0.f;
        for (int j = tid; j < deg; j += 32) {
            float e = expf(leaky(g1n + s_g2[j]) - mx);
            s_w[j] = e;
            sum += e;
        }
        #pragma unroll
        for (int off = 16; off; off >>= 1) sum += __shfl_xor_sync(0xffffffffu, sum, off);
        if (tid == 0) s_sum = sum;
    }
    __syncthreads();

    {
        int o = tid & 63, part = tid >> 6;
        float acc = 0.f;
        for (int j = part; j < deg; j += 4)
            acc += s_w[j] * d_Wh2[(size_t)s_idx[j] * 64 + o];
        s_part[part][o] = acc;
    }
    __syncthreads();
    if (tid < 64)
        s_h2[tid] = (s_part[0][tid] + s_part[1][tid] + s_part[2][tid] + s_part[3][tid]) / s_sum;
    __syncthreads();

    if (tid < 200) {
        float acc = fc1_b[tid];
        #pragma unroll 8
        for (int f = 0; f < 64; f++) acc += s_h2[f] * fc1_w[f * 200 + tid];
        s_h3[tid] = elu1(acc);
    }
    __syncthreads();

    if (tid < 200) {
        int c = tid % 40, part = tid / 40;
        float acc = 0.f;
        for (int k = part; k < 200; k += 5) acc += s_h3[k] * fc2_w[k * 40 + c];
        s_p2[part][c] = acc;
    }
    __syncthreads();
    if (tid < 40)
        out[(size_t)n * 40 + tid] =
            s_p2[0][tid] + s_p2[1][tid] + s_p2[2][tid] + s_p2[3][tid] + s_p2[4][tid] + fc2_b[tid];
}

// ---------------- launch ----------------------------------------------------
extern "C" void kernel_launch(void* const* d_in, const int* in_sizes, int n_in,
                              void* d_out, int out_size) {
    const float* x     = (const float*)d_in[0];
    const float* adj   = (const float*)d_in[1];
    const float* W_h   = (const float*)d_in[2];
    const float* a_h   = (const float*)d_in[3];
    const float* W_o   = (const float*)d_in[4];
    const float* a_o   = (const float*)d_in[5];
    const float* fc1_w = (const float*)d_in[6];
    const float* fc1_b = (const float*)d_in[7];
    const float* fc2_w = (const float*)d_in[8];
    const float* fc2_b = (const float*)d_in[9];
    float* out = (float*)d_out;

    void *pWh, *pH1, *pWh2, *pBt1, *pBt2, *pF1, *pF2, *pG1, *pG2;
    cudaGetSymbolAddress(&pWh,  d_Wh);
    cudaGetSymbolAddress(&pH1,  d_h1);
    cudaGetSymbolAddress(&pWh2, d_Wh2);
    cudaGetSymbolAddress(&pBt1, d_Bt1);
    cudaGetSymbolAddress(&pBt2, d_Bt2);
    cudaGetSymbolAddress(&pF1,  d_f1);
    cudaGetSymbolAddress(&pF2,  d_f2);
    cudaGetSymbolAddress(&pG1,  d_g1);
    cudaGetSymbolAddress(&pG2,  d_g2);

    const int MB = (NN + 127) / 128;   // 40

    // fork: build_csr (DRAM-bound) runs parallel to the GEMM path (tensor-bound)
    cudaStream_t s2;
    cudaStreamCreateWithFlags(&s2, cudaStreamNonBlocking);
    cudaEvent_t e0, e1;
    cudaEventCreateWithFlags(&e0, cudaEventDisableTiming);
    cudaEventCreateWithFlags(&e1, cudaEventDisableTiming);

    cudaEventRecord(e0, 0);
    cudaStreamWaitEvent(s2, e0, 0);
    gat_build_csr<<<NN, 256, 0, s2>>>(adj);
    cudaEventRecord(e1, s2);

    gat_pack_Bt1<<<512 * 512 / 256, 256>>>(W_h);
    gat_pack_Bt2<<<64 * 512 / 256, 256>>>(W_o);
    gat_mma_gemm<128><<<dim3(MB, 4), 256>>>(x, (const float*)pBt1, (float*)pWh, NN, 512,
                                            a_h, (float*)pF1, (float*)pF2);
    cudaStreamWaitEvent(0, e1, 0);   // join csr before agg1
    gat_agg1<<<NN, 256>>>();
    gat_mma_gemm<64><<<dim3(MB, 1), 256>>>((const float*)pH1, (const float*)pBt2, (float*)pWh2,
                                           NN, 64, a_o, (float*)pG1, (float*)pG2);
    gat_agg2_mlp<<<NN, 256>>>(fc1_w, fc1_b, fc2_w, fc2_b, out);

    cudaEventDestroy(e0);
    cudaEventDestroy(e1);
    cudaStreamDestroy(s2);
}

// round 5
// speedup vs baseline: 1.4574x; 1.1226x over previous
#include <cuda_runtime.h>
#include <math.h>
#include <cstdint>

#define NN 5000
#define NFEAT 512
#define NHID 64
#define NHEADS 8
#define NCLASS 40
#define LRALPHA 0.2f
#define MAXDEG 128

// ---------------- device scratch (no allocations allowed) ----------------
__device__ float d_Wh [NN * NHEADS * NHID];   // [N, 512] fp32
__device__ float d_h1 [NN * NHEADS * NHID];   // [N, 512] tf32-rounded elu output
__device__ float d_xt [NN * NFEAT];           // x converted to tf32
__device__ float d_Wh2[NN * NHID];            // [N, 64] fp32
__device__ float d_Bt1[512 * 512];            // packed W_h^T  [n=h*64+o][k], tf32
__device__ float d_Bt2[64 * 512];             // packed W_o^T  [n][k], tf32
__device__ float d_f1 [NHEADS * NN];
__device__ float d_f2 [NHEADS * NN];
__device__ float d_g1 [NN];
__device__ float d_g2 [NN];
__device__ int   d_nbr[NN * MAXDEG];
__device__ int   d_cnt[NN];

__device__ __forceinline__ float leaky(float t) { return t > 0.f ? t : LRALPHA * t; }
__device__ __forceinline__ float elu1(float t)  { return t > 0.f ? t : expf(t) - 1.f; }
__device__ __forceinline__ uint32_t f2tf32(float f) {
    uint32_t u;
    asm("cvt.rna.tf32.f32 %0, %1;" : "=r"(u) : "f"(f));
    return u;
}
__device__ __forceinline__ void mma_tf32(float& c0, float& c1, float& c2, float& c3,
                                         uint32_t a0, uint32_t a1, uint32_t a2, uint32_t a3,
                                         uint32_t b0, uint32_t b1) {
    asm volatile("mma.sync.aligned.m16n8k8.row.col.f32.tf32.tf32.f32 "
                 "{%0,%1,%2,%3}, {%4,%5,%6,%7}, {%8,%9}, {%0,%1,%2,%3};"
                 : "+f"(c0), "+f"(c1), "+f"(c2), "+f"(c3)
                 : "r"(a0), "r"(a1), "r"(a2), "r"(a3), "r"(b0), "r"(b1));
}
__device__ __forceinline__ void cp16(uint32_t dst, const void* src, bool p) {
    int sz = p ? 16 : 0;
    asm volatile("cp.async.cg.shared.global [%0], [%1], 16, %2;"
                 :: "r"(dst), "l"(src), "r"(sz) : "memory");
}
#define CP_COMMIT() asm volatile("cp.async.commit_group;" ::: "memory")

// ---------------- K0: adjacency -> neighbor lists --------------------------
__global__ void gat_build_csr(const float* __restrict__ adj) {
    int n = blockIdx.x;
    __shared__ int cnt;
    if (threadIdx.x == 0) cnt = 0;
    __syncthreads();
    const float4* row = reinterpret_cast<const float4*>(adj + (size_t)n * NN);
    for (int i = threadIdx.x; i < NN / 4; i += blockDim.x) {
        float4 v = row[i];
        int c = i * 4;
        if (v.x != 0.f) { int p = atomicAdd(&cnt, 1); if (p < MAXDEG) d_nbr[n * MAXDEG + p] = c;     }
        if (v.y != 0.f) { int p = atomicAdd(&cnt, 1); if (p < MAXDEG) d_nbr[n * MAXDEG + p] = c + 1; }
        if (v.z != 0.f) { int p = atomicAdd(&cnt, 1); if (p < MAXDEG) d_nbr[n * MAXDEG + p] = c + 2; }
        if (v.w != 0.f) { int p = atomicAdd(&cnt, 1); if (p < MAXDEG) d_nbr[n * MAXDEG + p] = c + 3; }
    }
    __syncthreads();
    if (threadIdx.x == 0) d_cnt[n] = min(cnt, MAXDEG);
}

// ---------------- packing / conversion kernels -----------------------------
__global__ void gat_pack_Bt1(const float* __restrict__ W_h) {
    int idx = blockIdx.x * 256 + threadIdx.x;        // 512*512
    int n = idx >> 9, k = idx & 511;
    int h = n >> 6, o = n & 63;
    d_Bt1[idx] = __uint_as_float(f2tf32(W_h[h * NFEAT * NHID + k * NHID + o]));
}
__global__ void gat_pack_Bt2(const float* __restrict__ W_o) {
    int idx = blockIdx.x * 256 + threadIdx.x;        // 64*512
    int n = idx >> 9, k = idx & 511;
    d_Bt2[idx] = __uint_as_float(f2tf32(W_o[k * NHID + n]));
}
__global__ void gat_cvt_x(const float* __restrict__ x) {
    int idx = blockIdx.x * 256 + threadIdx.x;        // float4 index
    float4 v = reinterpret_cast<const float4*>(x)[idx];
    uint4 u;
    u.x = f2tf32(v.x); u.y = f2tf32(v.y); u.z = f2tf32(v.z); u.w = f2tf32(v.w);
    reinterpret_cast<uint4*>(d_xt)[idx] = u;
}

// ---------------- tf32 HMMA GEMM, cp.async double-buffered -----------------
// A is pre-converted tf32 [M,512]; Bt is tf32 [Ntot,512].
// C[m, n0+j] = sum_k A[m,k]*Bt[n0+j,k];  fused f1/f2 = C-slice . av halves.
#define SPAD 36
template<int NT>
__global__ void __launch_bounds__(256) gat_mma_gemm(
        const float* __restrict__ A, const float* __restrict__ Bt,
        float* __restrict__ C, int M, int ldc,
        const float* __restrict__ av, float* __restrict__ f1o, float* __restrict__ f2o) {
    constexpr int WARPS_M = (NT == 128) ? 4 : 8;
    constexpr int WM = 128 / WARPS_M;      // 32 or 16
    constexpr int MT = WM / 16;            // 2 or 1
    constexpr int ASZ = (NT == 128) ? 256 : 128;
    constexpr int AW = 128 * SPAD;         // words per A buffer
    constexpr int BW = NT * SPAD;          // words per B buffer

    extern __shared__ float smemf[];
    float*    s_a = smemf;
    uint32_t* As  = reinterpret_cast<uint32_t*>(smemf + ASZ);
    uint32_t* Bs  = As + 2 * AW;

    int tid = threadIdx.x, w = tid >> 5, l = tid & 31;
    int m0 = blockIdx.x * 128, n0 = blockIdx.y * NT;
    int wm = w % WARPS_M, wn = w / WARPS_M;
    int mbase = wm * WM, nbase = wn * 64;

    if (tid < ASZ) s_a[tid] = av[(NT == 128 ? blockIdx.y * 256 : 0) + tid];

    float acc[MT][8][4];
    #pragma unroll
    for (int i = 0; i < MT; i++)
        #pragma unroll
        for (int j = 0; j < 8; j++)
            #pragma unroll
            for (int q = 0; q < 4; q++) acc[i][j][q] = 0.f;

    int lq = l >> 2, lr = l & 3;

    auto issue = [&](int kt, int b) {
        int k0 = kt * 32;
        #pragma unroll
        for (int i = 0; i < 4; i++) {
            int f = tid + i * 256;
            int r = f >> 3, c4 = (f & 7) * 4;
            int m = m0 + r;
            bool p = m < M;
            const float* src = A + (size_t)(p ? m : 0) * 512 + k0 + c4;
            cp16((uint32_t)__cvta_generic_to_shared(As + b * AW + r * SPAD + c4), src, p);
        }
        #pragma unroll
        for (int i = 0; i < NT / 32; i++) {
            int f = tid + i * 256;
            int r = f >> 3, c4 = (f & 7) * 4;
            const float* src = Bt + (size_t)(n0 + r) * 512 + k0 + c4;
            cp16((uint32_t)__cvta_generic_to_shared(Bs + b * BW + r * SPAD + c4), src, true);
        }
    };

    issue(0, 0);
    CP_COMMIT();

    for (int kt = 0; kt < 16; kt++) {
        if (kt + 1 < 16) {
            issue(kt + 1, (kt + 1) & 1);
            CP_COMMIT();
            asm volatile("cp.async.wait_group 1;" ::: "memory");
        } else {
            asm volatile("cp.async.wait_group 0;" ::: "memory");
        }
        __syncthreads();

        int b = kt & 1;
        const uint32_t* Ab = As + b * AW;
        const uint32_t* Bb = Bs + b * BW;
        #pragma unroll
        for (int ks = 0; ks < 4; ks++) {
            int kc = ks * 8 + lr;
            uint32_t af[MT][4];
            #pragma unroll
            for (int mt = 0; mt < MT; mt++) {
                const uint32_t* ap = Ab + (mbase + mt * 16 + lq) * SPAD;
                af[mt][0] = ap[kc];
                af[mt][1] = ap[8 * SPAD + kc];
                af[mt][2] = ap[kc + 4];
                af[mt][3] = ap[8 * SPAD + kc + 4];
            }
            #pragma unroll
            for (int nt = 0; nt < 8; nt++) {
                const uint32_t* bp = Bb + (nbase + nt * 8 + lq) * SPAD;
                uint32_t b0 = bp[kc];
                uint32_t b1 = bp[kc + 4];
                #pragma unroll
                for (int mt = 0; mt < MT; mt++)
                    mma_tf32(acc[mt][nt][0], acc[mt][nt][1], acc[mt][nt][2], acc[mt][nt][3],
                             af[mt][0], af[mt][1], af[mt][2], af[mt][3], b0, b1);
            }
        }
        __syncthreads();
    }

    // epilogue: store C
    #pragma unroll
    for (int mt = 0; mt < MT; mt++) {
        int r0 = m0 + mbase + mt * 16 + lq;
        int r1 = r0 + 8;
        #pragma unroll
        for (int nt = 0; nt < 8; nt++) {
            int c = n0 + nbase + nt * 8 + lr * 2;
            if (r0 < M)
                *reinterpret_cast<float2*>(C + (size_t)r0 * ldc + c) =
                    make_float2(acc[mt][nt][0], acc[mt][nt][1]);
            if (r1 < M)
                *reinterpret_cast<float2*>(C + (size_t)r1 * ldc + c) =
                    make_float2(acc[mt][nt][2], acc[mt][nt][3]);
        }
    }

    // fused attention-vector dot products (f1/f2 or g1/g2)
    {
        const float* va = s_a + ((NT == 128) ? wn * 128 : 0);
        float p1[MT][2] = {}, p2[MT][2] = {};
        #pragma unroll
        for (int nt = 0; nt < 8; nt++) {
            int o = nt * 8 + lr * 2;
            float a1x = va[o], a1y = va[o + 1];
            float a2x = va[64 + o], a2y = va[64 + o + 1];
            #pragma unroll
            for (int mt = 0; mt < MT; mt++) {
                p1[mt][0] += acc[mt][nt][0] * a1x + acc[mt][nt][1] * a1y;
                p2[mt][0] += acc[mt][nt][0] * a2x + acc[mt][nt][1] * a2y;
                p1[mt][1] += acc[mt][nt][2] * a1x + acc[mt][nt][3] * a1y;
                p2[mt][1] += acc[mt][nt][2] * a2x + acc[mt][nt][3] * a2y;
            }
        }
        #pragma unroll
        for (int mt = 0; mt < MT; mt++)
            #pragma unroll
            for (int rr = 0; rr < 2; rr++) {
                p1[mt][rr] += __shfl_xor_sync(0xffffffffu, p1[mt][rr], 1);
                p1[mt][rr] += __shfl_xor_sync(0xffffffffu, p1[mt][rr], 2);
                p2[mt][rr] += __shfl_xor_sync(0xffffffffu, p2[mt][rr], 1);
                p2[mt][rr] += __shfl_xor_sync(0xffffffffu, p2[mt][rr], 2);
            }
        if (lr == 0) {
            size_t hoff = (NT == 128) ? (size_t)(blockIdx.y * 2 + wn) * NN : 0;
            #pragma unroll
            for (int mt = 0; mt < MT; mt++) {
                int r0 = m0 + mbase + mt * 16 + lq;
                int r1 = r0 + 8;
                if (r0 < M) { f1o[hoff + r0] = p1[mt][0]; f2o[hoff + r0] = p2[mt][0]; }
                if (r1 < M) { f1o[hoff + r1] = p1[mt][1]; f2o[hoff + r1] = p2[mt][1]; }
            }
        }
    }
}

// ---------------- K3: layer-1 sparse attention + aggregation + elu --------
__global__ void gat_agg1() {
    int n = blockIdx.x;
    __shared__ int   s_idx[MAXDEG];
    __shared__ float s_f2[NHEADS][MAXDEG];
    __shared__ float s_w [NHEADS][MAXDEG];
    int tid = threadIdx.x;
    int deg = d_cnt[n];

    for (int j = tid; j < deg; j += 256) s_idx[j] = d_nbr[n * MAXDEG + j];
    __syncthreads();
    for (int t = tid; t < deg * NHEADS; t += 256) {
        int h = t / deg, j = t - h * deg;
        s_f2[h][j] = d_f2[h * NN + s_idx[j]];
    }
    __syncthreads();

    int w = tid >> 5, lane = tid & 31;
    float f1v = d_f1[w * NN + n];

    float mx = -1e30f;
    for (int j = lane; j < deg; j += 32) mx = fmaxf(mx, leaky(f1v + s_f2[w][j]));
    #pragma unroll
    for (int off = 16; off; off >>= 1) mx = fmaxf(mx, __shfl_xor_sync(0xffffffffu, mx, off));

    float sum = 0.f;
    for (int j = lane; j < deg; j += 32) {
        float e = expf(leaky(f1v + s_f2[w][j]) - mx);
        s_w[w][j] = e;
        sum += e;
    }
    #pragma unroll
    for (int off = 16; off; off >>= 1) sum += __shfl_xor_sync(0xffffffffu, sum, off);
    __syncwarp();

    float accx = 0.f, accy = 0.f;
    for (int j = 0; j < deg; j++) {
        float wj = s_w[w][j];
        float2 v = reinterpret_cast<const float2*>(d_Wh + (size_t)s_idx[j] * 512 + w * 64)[lane];
        accx += wj * v.x;
        accy += wj * v.y;
    }
    float inv = 1.f / sum;
    uint2 o = make_uint2(f2tf32(elu1(accx * inv)), f2tf32(elu1(accy * inv)));
    reinterpret_cast<uint2*>(d_h1 + (size_t)n * 512 + w * 64)[lane] = o;
}

// ---------------- K6: layer-2 attention + aggregation + MLP head ----------
__global__ void gat_agg2_mlp(const float* __restrict__ fc1_w, const float* __restrict__ fc1_b,
                             const float* __restrict__ fc2_w, const float* __restrict__ fc2_b,
                             float* __restrict__ out) {
    int n = blockIdx.x;
    __shared__ int   s_idx[MAXDEG];
    __shared__ float s_g2[MAXDEG];
    __shared__ float s_w [MAXDEG];
    __shared__ float s_sum;
    __shared__ float s_part[4][64];
    __shared__ float s_h2[64];
    __shared__ float s_h3[200];
    __shared__ float s_p2[5][40];
    int tid = threadIdx.x;
    int deg = d_cnt[n];

    for (int j = tid; j < deg; j += 256) {
        int c = d_nbr[n * MAXDEG + j];
        s_idx[j] = c;
        s_g2[j]  = d_g2[c];
    }
    __syncthreads();

    if (tid < 32) {
        float g1n = d_g1[n];
        float mx = -1e30f;
        for (int j = tid; j < deg; j += 32) mx = fmaxf(mx, leaky(g1n + s_g2[j]));
        #pragma unroll
        for (int off = 16; off; off >>= 1) mx = fmaxf(mx, __shfl_xor_sync(0xffffffffu, mx, off));
        float sum = 0.f;
        for (int j = tid; j < deg; j += 32) {
            float e = expf(leaky(g1n + s_g2[j]) - mx);
            s_w[j] = e;
            sum += e;
        }
        #pragma unroll
        for (int off = 16; off; off >>= 1) sum += __shfl_xor_sync(0xffffffffu, sum, off);
        if (tid == 0) s_sum = sum;
    }
    __syncthreads();

    {
        int o = tid & 63, part = tid >> 6;
        float acc = 0.f;
        for (int j = part; j < deg; j += 4)
            acc += s_w[j] * d_Wh2[(size_t)s_idx[j] * 64 + o];
        s_part[part][o] = acc;
    }
    __syncthreads();
    if (tid < 64)
        s_h2[tid] = (s_part[0][tid] + s_part[1][tid] + s_part[2][tid] + s_part[3][tid]) / s_sum;
    __syncthreads();

    if (tid < 200) {
        float acc = fc1_b[tid];
        #pragma unroll 8
        for (int f = 0; f < 64; f++) acc += s_h2[f] * fc1_w[f * 200 + tid];
        s_h3[tid] = elu1(acc);
    }
    __syncthreads();

    if (tid < 200) {
        int c = tid % 40, part = tid / 40;
        float acc = 0.f;
        for (int k = part; k < 200; k += 5) acc += s_h3[k] * fc2_w[k * 40 + c];
        s_p2[part][c] = acc;
    }
    __syncthreads();
    if (tid < 40)
        out[(size_t)n * 40 + tid] =
            s_p2[0][tid] + s_p2[1][tid] + s_p2[2][tid] + s_p2[3][tid] + s_p2[4][tid] + fc2_b[tid];
}

// ---------------- launch ----------------------------------------------------
extern "C" void kernel_launch(void* const* d_in, const int* in_sizes, int n_in,
                              void* d_out, int out_size) {
    const float* x     = (const float*)d_in[0];
    const float* adj   = (const float*)d_in[1];
    const float* W_h   = (const float*)d_in[2];
    const float* a_h   = (const float*)d_in[3];
    const float* W_o   = (const float*)d_in[4];
    const float* a_o   = (const float*)d_in[5];
    const float* fc1_w = (const float*)d_in[6];
    const float* fc1_b = (const float*)d_in[7];
    const float* fc2_w = (const float*)d_in[8];
    const float* fc2_b = (const float*)d_in[9];
    float* out = (float*)d_out;

    void *pWh, *pH1, *pXt, *pWh2, *pBt1, *pBt2, *pF1, *pF2, *pG1, *pG2;
    cudaGetSymbolAddress(&pWh,  d_Wh);
    cudaGetSymbolAddress(&pH1,  d_h1);
    cudaGetSymbolAddress(&pXt,  d_xt);
    cudaGetSymbolAddress(&pWh2, d_Wh2);
    cudaGetSymbolAddress(&pBt1, d_Bt1);
    cudaGetSymbolAddress(&pBt2, d_Bt2);
    cudaGetSymbolAddress(&pF1,  d_f1);
    cudaGetSymbolAddress(&pF2,  d_f2);
    cudaGetSymbolAddress(&pG1,  d_g1);
    cudaGetSymbolAddress(&pG2,  d_g2);

    const int MB = (NN + 127) / 128;   // 40
    const int SMEM128 = (256 + 4 * 128 * SPAD) * 4;          // 74752
    const int SMEM64  = (128 + 2 * 128 * SPAD + 2 * 64 * SPAD) * 4; // 55808
    cudaFuncSetAttribute(gat_mma_gemm<128>, cudaFuncAttributeMaxDynamicSharedMemorySize, SMEM128);
    cudaFuncSetAttribute(gat_mma_gemm<64>,  cudaFuncAttributeMaxDynamicSharedMemorySize, SMEM64);

    // fork: build_csr (DRAM-bound) runs parallel to the GEMM path (tensor-bound)
    cudaStream_t s2;
    cudaStreamCreateWithFlags(&s2, cudaStreamNonBlocking);
    cudaEvent_t e0, e1;
    cudaEventCreateWithFlags(&e0, cudaEventDisableTiming);
    cudaEventCreateWithFlags(&e1, cudaEventDisableTiming);

    cudaEventRecord(e0, 0);
    cudaStreamWaitEvent(s2, e0, 0);
    gat_build_csr<<<NN, 256, 0, s2>>>(adj);
    cudaEventRecord(e1, s2);

    gat_cvt_x<<<NN * NFEAT / 4 / 256, 256>>>(x);
    gat_pack_Bt1<<<512 * 512 / 256, 256>>>(W_h);
    gat_pack_Bt2<<<64 * 512 / 256, 256>>>(W_o);
    gat_mma_gemm<128><<<dim3(MB, 4), 256, SMEM128>>>((const float*)pXt, (const float*)pBt1,
                                                     (float*)pWh, NN, 512,
                                                     a_h, (float*)pF1, (float*)pF2);
    cudaStreamWaitEvent(0, e1, 0);   // join csr before agg1
    gat_agg1<<<NN, 256>>>();
    gat_mma_gemm<64><<<dim3(MB, 1), 256, SMEM64>>>((const float*)pH1, (const float*)pBt2,
                                                   (float*)pWh2, NN, 64,
                                                   a_o, (float*)pG1, (float*)pG2);
    gat_agg2_mlp<<<NN, 256>>>(fc1_w, fc1_b, fc2_w, fc2_b, out);

    cudaEventDestroy(e0);
    cudaEventDestroy(e1);
    cudaStreamDestroy(s2);
}

// round 6
// speedup vs baseline: 1.5058x; 1.0332x over previous
#include <cuda_runtime.h>
#include <cuda_fp16.h>
#include <math.h>
#include <cstdint>

#define NN 5000
#define NFEAT 512
#define NHID 64
#define NHEADS 8
#define NCLASS 40
#define LRALPHA 0.2f
#define MAXDEG 128

// ---------------- device scratch (no allocations allowed) ----------------
__device__ __half2 d_Whh[NN * 256];          // Wh as half2 [N, 256 pairs]
__device__ float d_h1 [NN * NHEADS * NHID];   // [N, 512] tf32-rounded elu output
__device__ float d_xt [NN * NFEAT];           // x converted to tf32
__device__ float d_Wh2[NN * NHID];            // [N, 64] fp32
__device__ float d_Bt1[512 * 512];            // packed W_h^T  [n=h*64+o][k], tf32
__device__ float d_Bt2[64 * 512];             // packed W_o^T  [n][k], tf32
__device__ float d_f1 [NHEADS * NN];
__device__ float d_f2 [NHEADS * NN];
__device__ float d_g1 [NN];
__device__ float d_g2 [NN];
__device__ int   d_nbr[NN * MAXDEG];
__device__ int   d_cnt[NN];

__device__ __forceinline__ float leaky(float t) { return t > 0.f ? t : LRALPHA * t; }
__device__ __forceinline__ float elu1(float t)  { return t > 0.f ? t : expf(t) - 1.f; }
__device__ __forceinline__ uint32_t f2tf32(float f) {
    uint32_t u;
    asm("cvt.rna.tf32.f32 %0, %1;" : "=r"(u) : "f"(f));
    return u;
}
__device__ __forceinline__ void mma_tf32(float& c0, float& c1, float& c2, float& c3,
                                         uint32_t a0, uint32_t a1, uint32_t a2, uint32_t a3,
                                         uint32_t b0, uint32_t b1) {
    asm volatile("mma.sync.aligned.m16n8k8.row.col.f32.tf32.tf32.f32 "
                 "{%0,%1,%2,%3}, {%4,%5,%6,%7}, {%8,%9}, {%0,%1,%2,%3};"
                 : "+f"(c0), "+f"(c1), "+f"(c2), "+f"(c3)
                 : "r"(a0), "r"(a1), "r"(a2), "r"(a3), "r"(b0), "r"(b1));
}
__device__ __forceinline__ void cp16(uint32_t dst, const void* src, bool p) {
    int sz = p ? 16 : 0;
    asm volatile("cp.async.cg.shared.global [%0], [%1], 16, %2;"
                 :: "r"(dst), "l"(src), "r"(sz) : "memory");
}
#define CP_COMMIT() asm volatile("cp.async.commit_group;" ::: "memory")

// ---------------- K0: adjacency -> neighbor lists --------------------------
__global__ void gat_build_csr(const float* __restrict__ adj) {
    int n = blockIdx.x;
    __shared__ int cnt;
    if (threadIdx.x == 0) cnt = 0;
    __syncthreads();
    const float4* row = reinterpret_cast<const float4*>(adj + (size_t)n * NN);
    for (int i = threadIdx.x; i < NN / 4; i += blockDim.x) {
        float4 v = row[i];
        int c = i * 4;
        if (v.x != 0.f) { int p = atomicAdd(&cnt, 1); if (p < MAXDEG) d_nbr[n * MAXDEG + p] = c;     }
        if (v.y != 0.f) { int p = atomicAdd(&cnt, 1); if (p < MAXDEG) d_nbr[n * MAXDEG + p] = c + 1; }
        if (v.z != 0.f) { int p = atomicAdd(&cnt, 1); if (p < MAXDEG) d_nbr[n * MAXDEG + p] = c + 2; }
        if (v.w != 0.f) { int p = atomicAdd(&cnt, 1); if (p < MAXDEG) d_nbr[n * MAXDEG + p] = c + 3; }
    }
    __syncthreads();
    if (threadIdx.x == 0) d_cnt[n] = min(cnt, MAXDEG);
}

// ---------------- merged prep: cvt x + pack Bt1 + pack Bt2 -----------------
#define CVTX_BLOCKS (NN * NFEAT / 4 / 256)    // 2560
#define BT1_BLOCKS  (512 * 512 / 256)         // 1024
#define BT2_BLOCKS  (64 * 512 / 256)          // 128
__global__ void gat_prep(const float* __restrict__ x, const float* __restrict__ W_h,
                         const float* __restrict__ W_o) {
    int b = blockIdx.x, tid = threadIdx.x;
    if (b < CVTX_BLOCKS) {
        int idx = b * 256 + tid;
        float4 v = reinterpret_cast<const float4*>(x)[idx];
        uint4 u;
        u.x = f2tf32(v.x); u.y = f2tf32(v.y); u.z = f2tf32(v.z); u.w = f2tf32(v.w);
        reinterpret_cast<uint4*>(d_xt)[idx] = u;
    } else if (b < CVTX_BLOCKS + BT1_BLOCKS) {
        int idx = (b - CVTX_BLOCKS) * 256 + tid;
        int n = idx >> 9, k = idx & 511;
        int h = n >> 6, o = n & 63;
        d_Bt1[idx] = __uint_as_float(f2tf32(W_h[h * NFEAT * NHID + k * NHID + o]));
    } else {
        int idx = (b - CVTX_BLOCKS - BT1_BLOCKS) * 256 + tid;
        int n = idx >> 9, k = idx & 511;
        d_Bt2[idx] = __uint_as_float(f2tf32(W_o[k * NHID + n]));
    }
}

// ---------------- tf32 HMMA GEMM, cp.async double-buffered -----------------
// NT=128: C stored as half2 into d_Whh; NT=64: C stored fp32.
// Fused f1/f2 (or g1/g2) = C-slice . av halves.
#define SPAD 36
template<int NT>
__global__ void __launch_bounds__(256) gat_mma_gemm(
        const float* __restrict__ A, const float* __restrict__ Bt,
        void* __restrict__ Cout, int M, int ldc,
        const float* __restrict__ av, float* __restrict__ f1o, float* __restrict__ f2o) {
    constexpr int WARPS_M = (NT == 128) ? 4 : 8;
    constexpr int WM = 128 / WARPS_M;      // 32 or 16
    constexpr int MT = WM / 16;            // 2 or 1
    constexpr int ASZ = (NT == 128) ? 256 : 128;
    constexpr int AW = 128 * SPAD;
    constexpr int BW = NT * SPAD;

    extern __shared__ float smemf[];
    float*    s_a = smemf;
    uint32_t* As  = reinterpret_cast<uint32_t*>(smemf + ASZ);
    uint32_t* Bs  = As + 2 * AW;

    int tid = threadIdx.x, w = tid >> 5, l = tid & 31;
    int m0 = blockIdx.x * 128, n0 = blockIdx.y * NT;
    int wm = w % WARPS_M, wn = w / WARPS_M;
    int mbase = wm * WM, nbase = wn * 64;

    if (tid < ASZ) s_a[tid] = av[(NT == 128 ? blockIdx.y * 256 : 0) + tid];

    float acc[MT][8][4];
    #pragma unroll
    for (int i = 0; i < MT; i++)
        #pragma unroll
        for (int j = 0; j < 8; j++)
            #pragma unroll
            for (int q = 0; q < 4; q++) acc[i][j][q] = 0.f;

    int lq = l >> 2, lr = l & 3;

    auto issue = [&](int kt, int b) {
        int k0 = kt * 32;
        #pragma unroll
        for (int i = 0; i < 4; i++) {
            int f = tid + i * 256;
            int r = f >> 3, c4 = (f & 7) * 4;
            int m = m0 + r;
            bool p = m < M;
            const float* src = A + (size_t)(p ? m : 0) * 512 + k0 + c4;
            cp16((uint32_t)__cvta_generic_to_shared(As + b * AW + r * SPAD + c4), src, p);
        }
        #pragma unroll
        for (int i = 0; i < NT / 32; i++) {
            int f = tid + i * 256;
            int r = f >> 3, c4 = (f & 7) * 4;
            const float* src = Bt + (size_t)(n0 + r) * 512 + k0 + c4;
            cp16((uint32_t)__cvta_generic_to_shared(Bs + b * BW + r * SPAD + c4), src, true);
        }
    };

    issue(0, 0);
    CP_COMMIT();

    for (int kt = 0; kt < 16; kt++) {
        if (kt + 1 < 16) {
            issue(kt + 1, (kt + 1) & 1);
            CP_COMMIT();
            asm volatile("cp.async.wait_group 1;" ::: "memory");
        } else {
            asm volatile("cp.async.wait_group 0;" ::: "memory");
        }
        __syncthreads();

        int b = kt & 1;
        const uint32_t* Ab = As + b * AW;
        const uint32_t* Bb = Bs + b * BW;
        #pragma unroll
        for (int ks = 0; ks < 4; ks++) {
            int kc = ks * 8 + lr;
            uint32_t af[MT][4];
            #pragma unroll
            for (int mt = 0; mt < MT; mt++) {
                const uint32_t* ap = Ab + (mbase + mt * 16 + lq) * SPAD;
                af[mt][0] = ap[kc];
                af[mt][1] = ap[8 * SPAD + kc];
                af[mt][2] = ap[kc + 4];
                af[mt][3] = ap[8 * SPAD + kc + 4];
            }
            #pragma unroll
            for (int nt = 0; nt < 8; nt++) {
                const uint32_t* bp = Bb + (nbase + nt * 8 + lq) * SPAD;
                uint32_t b0 = bp[kc];
                uint32_t b1 = bp[kc + 4];
                #pragma unroll
                for (int mt = 0; mt < MT; mt++)
                    mma_tf32(acc[mt][nt][0], acc[mt][nt][1], acc[mt][nt][2], acc[mt][nt][3],
                             af[mt][0], af[mt][1], af[mt][2], af[mt][3], b0, b1);
            }
        }
        __syncthreads();
    }

    // epilogue: store C (half2 for layer-1 Wh, fp32 for layer-2 Wh2)
    #pragma unroll
    for (int mt = 0; mt < MT; mt++) {
        int r0 = m0 + mbase + mt * 16 + lq;
        int r1 = r0 + 8;
        #pragma unroll
        for (int nt = 0; nt < 8; nt++) {
            int c = n0 + nbase + nt * 8 + lr * 2;
            if (NT == 128) {
                __half2* Ch = reinterpret_cast<__half2*>(Cout);
                if (r0 < M) Ch[(size_t)r0 * 256 + (c >> 1)] =
                    __floats2half2_rn(acc[mt][nt][0], acc[mt][nt][1]);
                if (r1 < M) Ch[(size_t)r1 * 256 + (c >> 1)] =
                    __floats2half2_rn(acc[mt][nt][2], acc[mt][nt][3]);
            } else {
                float* Cf = reinterpret_cast<float*>(Cout);
                if (r0 < M)
                    *reinterpret_cast<float2*>(Cf + (size_t)r0 * ldc + c) =
                        make_float2(acc[mt][nt][0], acc[mt][nt][1]);
                if (r1 < M)
                    *reinterpret_cast<float2*>(Cf + (size_t)r1 * ldc + c) =
                        make_float2(acc[mt][nt][2], acc[mt][nt][3]);
            }
        }
    }

    // fused attention-vector dot products (f1/f2 or g1/g2)
    {
        const float* va = s_a + ((NT == 128) ? wn * 128 : 0);
        float p1[MT][2] = {}, p2[MT][2] = {};
        #pragma unroll
        for (int nt = 0; nt < 8; nt++) {
            int o = nt * 8 + lr * 2;
            float a1x = va[o], a1y = va[o + 1];
            float a2x = va[64 + o], a2y = va[64 + o + 1];
            #pragma unroll
            for (int mt = 0; mt < MT; mt++) {
                p1[mt][0] += acc[mt][nt][0] * a1x + acc[mt][nt][1] * a1y;
                p2[mt][0] += acc[mt][nt][0] * a2x + acc[mt][nt][1] * a2y;
                p1[mt][1] += acc[mt][nt][2] * a1x + acc[mt][nt][3] * a1y;
                p2[mt][1] += acc[mt][nt][2] * a2x + acc[mt][nt][3] * a2y;
            }
        }
        #pragma unroll
        for (int mt = 0; mt < MT; mt++)
            #pragma unroll
            for (int rr = 0; rr < 2; rr++) {
                p1[mt][rr] += __shfl_xor_sync(0xffffffffu, p1[mt][rr], 1);
                p1[mt][rr] += __shfl_xor_sync(0xffffffffu, p1[mt][rr], 2);
                p2[mt][rr] += __shfl_xor_sync(0xffffffffu, p2[mt][rr], 1);
                p2[mt][rr] += __shfl_xor_sync(0xffffffffu, p2[mt][rr], 2);
            }
        if (lr == 0) {
            size_t hoff = (NT == 128) ? (size_t)(blockIdx.y * 2 + wn) * NN : 0;
            #pragma unroll
            for (int mt = 0; mt < MT; mt++) {
                int r0 = m0 + mbase + mt * 16 + lq;
                int r1 = r0 + 8;
                if (r0 < M) { f1o[hoff + r0] = p1[mt][0]; f2o[hoff + r0] = p2[mt][0]; }
                if (r1 < M) { f1o[hoff + r1] = p1[mt][1]; f2o[hoff + r1] = p2[mt][1]; }
            }
        }
    }
}

// ---------------- K3: layer-1 sparse attention + aggregation + elu --------
__global__ void gat_agg1() {
    int n = blockIdx.x;
    __shared__ int   s_idx[MAXDEG];
    __shared__ float s_f2[NHEADS][MAXDEG];
    __shared__ float s_w [NHEADS][MAXDEG];
    int tid = threadIdx.x;
    int deg = d_cnt[n];

    for (int j = tid; j < deg; j += 256) s_idx[j] = d_nbr[n * MAXDEG + j];
    __syncthreads();
    for (int t = tid; t < deg * NHEADS; t += 256) {
        int h = t / deg, j = t - h * deg;
        s_f2[h][j] = d_f2[h * NN + s_idx[j]];
    }
    __syncthreads();

    int w = tid >> 5, lane = tid & 31;
    float f1v = d_f1[w * NN + n];

    float mx = -1e30f;
    for (int j = lane; j < deg; j += 32) mx = fmaxf(mx, leaky(f1v + s_f2[w][j]));
    #pragma unroll
    for (int off = 16; off; off >>= 1) mx = fmaxf(mx, __shfl_xor_sync(0xffffffffu, mx, off));

    float sum = 0.f;
    for (int j = lane; j < deg; j += 32) {
        float e = expf(leaky(f1v + s_f2[w][j]) - mx);
        s_w[w][j] = e;
        sum += e;
    }
    #pragma unroll
    for (int off = 16; off; off >>= 1) sum += __shfl_xor_sync(0xffffffffu, sum, off);
    __syncwarp();

    float accx = 0.f, accy = 0.f;
    const __half2* whb = d_Whh + w * 32 + lane;
    for (int j = 0; j < deg; j++) {
        float wj = s_w[w][j];
        float2 v = __half22float2(whb[(size_t)s_idx[j] * 256]);
        accx += wj * v.x;
        accy += wj * v.y;
    }
    float inv = 1.f / sum;
    uint2 o = make_uint2(f2tf32(elu1(accx * inv)), f2tf32(elu1(accy * inv)));
    // h1 layout: [n][h*64 + {2*lane, 2*lane+1}] matches half2 pair ordering
    reinterpret_cast<uint2*>(d_h1 + (size_t)n * 512 + w * 64)[lane] = o;
}

// ---------------- K6: layer-2 attention + aggregation + MLP head ----------
__global__ void gat_agg2_mlp(const float* __restrict__ fc1_w, const float* __restrict__ fc1_b,
                             const float* __restrict__ fc2_w, const float* __restrict__ fc2_b,
                             float* __restrict__ out) {
    int n = blockIdx.x;
    __shared__ int   s_idx[MAXDEG];
    __shared__ float s_g2[MAXDEG];
    __shared__ float s_w [MAXDEG];
    __shared__ float s_sum;
    __shared__ float s_part[4][64];
    __shared__ float s_h2[64];
    __shared__ float s_h3[200];
    __shared__ float s_p2[5][40];
    int tid = threadIdx.x;
    int deg = d_cnt[n];

    for (int j = tid; j < deg; j += 256) {
        int c = d_nbr[n * MAXDEG + j];
        s_idx[j] = c;
        s_g2[j]  = d_g2[c];
    }
    __syncthreads();

    if (tid < 32) {
        float g1n = d_g1[n];
        float mx = -1e30f;
        for (int j = tid; j < deg; j += 32) mx = fmaxf(mx, leaky(g1n + s_g2[j]));
        #pragma unroll
        for (int off = 16; off; off >>= 1) mx = fmaxf(mx, __shfl_xor_sync(0xffffffffu, mx, off));
        float sum = 0.f;
        for (int j = tid; j < deg; j += 32) {
            float e = expf(leaky(g1n + s_g2[j]) - mx);
            s_w[j] = e;
            sum += e;
        }
        #pragma unroll
        for (int off = 16; off; off >>= 1) sum += __shfl_xor_sync(0xffffffffu, sum, off);
        if (tid == 0) s_sum = sum;
    }
    __syncthreads();

    {
        int o = tid & 63, part = tid >> 6;
        float acc = 0.f;
        for (int j = part; j < deg; j += 4)
            acc += s_w[j] * d_Wh2[(size_t)s_idx[j] * 64 + o];
        s_part[part][o] = acc;
    }
    __syncthreads();
    if (tid < 64)
        s_h2[tid] = (s_part[0][tid] + s_part[1][tid] + s_part[2][tid] + s_part[3][tid]) / s_sum;
    __syncthreads();

    if (tid < 200) {
        float acc = fc1_b[tid];
        #pragma unroll 8
        for (int f = 0; f < 64; f++) acc += s_h2[f] * fc1_w[f * 200 + tid];
        s_h3[tid] = elu1(acc);
    }
    __syncthreads();

    if (tid < 200) {
        int c = tid % 40, part = tid / 40;
        float acc = 0.f;
        for (int k = part; k < 200; k += 5) acc += s_h3[k] * fc2_w[k * 40 + c];
        s_p2[part][c] = acc;
    }
    __syncthreads();
    if (tid < 40)
        out[(size_t)n * 40 + tid] =
            s_p2[0][tid] + s_p2[1][tid] + s_p2[2][tid] + s_p2[3][tid] + s_p2[4][tid] + fc2_b[tid];
}

// ---------------- launch ----------------------------------------------------
extern "C" void kernel_launch(void* const* d_in, const int* in_sizes, int n_in,
                              void* d_out, int out_size) {
    const float* x     = (const float*)d_in[0];
    const float* adj   = (const float*)d_in[1];
    const float* W_h   = (const float*)d_in[2];
    const float* a_h   = (const float*)d_in[3];
    const float* W_o   = (const float*)d_in[4];
    const float* a_o   = (const float*)d_in[5];
    const float* fc1_w = (const float*)d_in[6];
    const float* fc1_b = (const float*)d_in[7];
    const float* fc2_w = (const float*)d_in[8];
    const float* fc2_b = (const float*)d_in[9];
    float* out = (float*)d_out;

    void *pWhh, *pH1, *pXt, *pWh2, *pBt1, *pBt2, *pF1, *pF2, *pG1, *pG2;
    cudaGetSymbolAddress(&pWhh, d_Whh);
    cudaGetSymbolAddress(&pH1,  d_h1);
    cudaGetSymbolAddress(&pXt,  d_xt);
    cudaGetSymbolAddress(&pWh2, d_Wh2);
    cudaGetSymbolAddress(&pBt1, d_Bt1);
    cudaGetSymbolAddress(&pBt2, d_Bt2);
    cudaGetSymbolAddress(&pF1,  d_f1);
    cudaGetSymbolAddress(&pF2,  d_f2);
    cudaGetSymbolAddress(&pG1,  d_g1);
    cudaGetSymbolAddress(&pG2,  d_g2);

    const int MB = (NN + 127) / 128;   // 40
    const int SMEM128 = (256 + 4 * 128 * SPAD) * 4;                 // 74752
    const int SMEM64  = (128 + 2 * 128 * SPAD + 2 * 64 * SPAD) * 4; // 55808
    cudaFuncSetAttribute(gat_mma_gemm<128>, cudaFuncAttributeMaxDynamicSharedMemorySize, SMEM128);
    cudaFuncSetAttribute(gat_mma_gemm<64>,  cudaFuncAttributeMaxDynamicSharedMemorySize, SMEM64);

    // fork: build_csr (DRAM-bound) runs parallel to the GEMM path (tensor-bound)
    cudaStream_t s2;
    cudaStreamCreateWithFlags(&s2, cudaStreamNonBlocking);
    cudaEvent_t e0, e1;
    cudaEventCreateWithFlags(&e0, cudaEventDisableTiming);
    cudaEventCreateWithFlags(&e1, cudaEventDisableTiming);

    cudaEventRecord(e0, 0);
    cudaStreamWaitEvent(s2, e0, 0);
    gat_build_csr<<<NN, 256, 0, s2>>>(adj);
    cudaEventRecord(e1, s2);

    gat_prep<<<CVTX_BLOCKS + BT1_BLOCKS + BT2_BLOCKS, 256>>>(x, W_h, W_o);
    gat_mma_gemm<128><<<dim3(MB, 4), 256, SMEM128>>>((const float*)pXt, (const float*)pBt1,
                                                     pWhh, NN, 512,
                                                     a_h, (float*)pF1, (float*)pF2);
    cudaStreamWaitEvent(0, e1, 0);   // join csr before agg1
    gat_agg1<<<NN, 256>>>();
    gat_mma_gemm<64><<<dim3(MB, 1), 256, SMEM64>>>((const float*)pH1, (const float*)pBt2,
                                                   pWh2, NN, 64,
                                                   a_o, (float*)pG1, (float*)pG2);
    gat_agg2_mlp<<<NN, 256>>>(fc1_w, fc1_b, fc2_w, fc2_b, out);

    cudaEventDestroy(e0);
    cudaEventDestroy(e1);
    cudaStreamDestroy(s2);
}

// round 7
// speedup vs baseline: 1.6559x; 1.0997x over previous
#include <cuda_runtime.h>
#include <cuda_fp16.h>
#include <math.h>
#include <cstdint>

#define NN 5000
#define NFEAT 512
#define NHID 64
#define NHEADS 8
#define NCLASS 40
#define LRALPHA 0.2f
#define MAXDEG 128

// ---------------- device scratch (no allocations allowed) ----------------
__device__ __half2 d_Whh[NN * 256];           // Wh as half2 [N, 256 pairs]
__device__ float d_h1 [NN * NHEADS * NHID];   // [N, 512] tf32 elu output
__device__ float d_xt [NN * NFEAT];           // x converted to tf32
__device__ float d_Wh2[NN * NHID];            // [N, 64] fp32
__device__ float d_h2 [NN * NHID];            // [N, 64] tf32
__device__ float d_h3 [NN * 256];             // [N, 256] tf32 (200 used)
__device__ float d_Bt1[512 * 512];            // W_h^T  [n=h*64+o][k], tf32
__device__ float d_Bt2[64 * 512];             // W_o^T  [n][k], tf32
__device__ float d_Bt3[256 * 64];             // fc1_w^T padded [n][k], tf32
__device__ float d_Bt4[64 * 256];             // fc2_w^T padded [n][k], tf32
__device__ float d_bias3[256];
__device__ float d_bias4[64];
__device__ float d_f1 [NHEADS * NN];
__device__ float d_f2 [NHEADS * NN];
__device__ float d_g1 [NN];
__device__ float d_g2 [NN];
__device__ int   d_nbr[NN * MAXDEG];
__device__ int   d_cnt[NN];

__device__ __forceinline__ float leaky(float t) { return t > 0.f ? t : LRALPHA * t; }
__device__ __forceinline__ float elu1(float t)  { return t > 0.f ? t : expf(t) - 1.f; }
__device__ __forceinline__ uint32_t f2tf32(float f) {
    uint32_t u;
    asm("cvt.rna.tf32.f32 %0, %1;" : "=r"(u) : "f"(f));
    return u;
}
__device__ __forceinline__ void mma_tf32(float& c0, float& c1, float& c2, float& c3,
                                         uint32_t a0, uint32_t a1, uint32_t a2, uint32_t a3,
                                         uint32_t b0, uint32_t b1) {
    asm volatile("mma.sync.aligned.m16n8k8.row.col.f32.tf32.tf32.f32 "
                 "{%0,%1,%2,%3}, {%4,%5,%6,%7}, {%8,%9}, {%0,%1,%2,%3};"
                 : "+f"(c0), "+f"(c1), "+f"(c2), "+f"(c3)
                 : "r"(a0), "r"(a1), "r"(a2), "r"(a3), "r"(b0), "r"(b1));
}
__device__ __forceinline__ void cp16(uint32_t dst, const void* src, bool p) {
    int sz = p ? 16 : 0;
    asm volatile("cp.async.cg.shared.global [%0], [%1], 16, %2;"
                 :: "r"(dst), "l"(src), "r"(sz) : "memory");
}
#define CP_COMMIT() asm volatile("cp.async.commit_group;" ::: "memory")

// ---------------- K0: adjacency -> neighbor lists --------------------------
__global__ void gat_build_csr(const float* __restrict__ adj) {
    int n = blockIdx.x;
    __shared__ int cnt;
    if (threadIdx.x == 0) cnt = 0;
    __syncthreads();
    const float4* row = reinterpret_cast<const float4*>(adj + (size_t)n * NN);
    for (int i = threadIdx.x; i < NN / 4; i += blockDim.x) {
        float4 v = row[i];
        int c = i * 4;
        if (v.x != 0.f) { int p = atomicAdd(&cnt, 1); if (p < MAXDEG) d_nbr[n * MAXDEG + p] = c;     }
        if (v.y != 0.f) { int p = atomicAdd(&cnt, 1); if (p < MAXDEG) d_nbr[n * MAXDEG + p] = c + 1; }
        if (v.z != 0.f) { int p = atomicAdd(&cnt, 1); if (p < MAXDEG) d_nbr[n * MAXDEG + p] = c + 2; }
        if (v.w != 0.f) { int p = atomicAdd(&cnt, 1); if (p < MAXDEG) d_nbr[n * MAXDEG + p] = c + 3; }
    }
    __syncthreads();
    if (threadIdx.x == 0) d_cnt[n] = min(cnt, MAXDEG);
}

// ---------------- merged prep ----------------------------------------------
#define CVTX_BLOCKS (NN * NFEAT / 4 / 256)    // 2560
#define BT1_BLOCKS  (512 * 512 / 256)         // 1024
#define BT2_BLOCKS  (64 * 512 / 256)          // 128
#define BT3_BLOCKS  (256 * 64 / 256)          // 64
#define BT4_BLOCKS  (64 * 256 / 256)          // 64
#define PREP_BLOCKS (CVTX_BLOCKS + BT1_BLOCKS + BT2_BLOCKS + BT3_BLOCKS + BT4_BLOCKS + 1)
__global__ void gat_prep(const float* __restrict__ x, const float* __restrict__ W_h,
                         const float* __restrict__ W_o,
                         const float* __restrict__ fc1_w, const float* __restrict__ fc1_b,
                         const float* __restrict__ fc2_w, const float* __restrict__ fc2_b) {
    int b = blockIdx.x, tid = threadIdx.x;
    if (b < CVTX_BLOCKS) {
        int idx = b * 256 + tid;
        float4 v = reinterpret_cast<const float4*>(x)[idx];
        uint4 u;
        u.x = f2tf32(v.x); u.y = f2tf32(v.y); u.z = f2tf32(v.z); u.w = f2tf32(v.w);
        reinterpret_cast<uint4*>(d_xt)[idx] = u;
    } else if ((b -= CVTX_BLOCKS) < BT1_BLOCKS) {
        int idx = b * 256 + tid;
        int n = idx >> 9, k = idx & 511;
        int h = n >> 6, o = n & 63;
        d_Bt1[idx] = __uint_as_float(f2tf32(W_h[h * NFEAT * NHID + k * NHID + o]));
    } else if ((b -= BT1_BLOCKS) < BT2_BLOCKS) {
        int idx = b * 256 + tid;
        int n = idx >> 9, k = idx & 511;
        d_Bt2[idx] = __uint_as_float(f2tf32(W_o[k * NHID + n]));
    } else if ((b -= BT2_BLOCKS) < BT3_BLOCKS) {
        int idx = b * 256 + tid;
        int n = idx >> 6, k = idx & 63;
        d_Bt3[idx] = (n < 200) ? __uint_as_float(f2tf32(fc1_w[k * 200 + n])) : 0.f;
    } else if ((b -= BT3_BLOCKS) < BT4_BLOCKS) {
        int idx = b * 256 + tid;
        int n = idx >> 8, k = idx & 255;
        d_Bt4[idx] = (n < 40 && k < 200) ? __uint_as_float(f2tf32(fc2_w[k * 40 + n])) : 0.f;
    } else {
        d_bias3[tid] = (tid < 200) ? fc1_b[tid] : 0.f;
        if (tid < 64) d_bias4[tid] = (tid < 40) ? fc2_b[tid] : 0.f;
    }
}

// ---------------- tf32 HMMA GEMM, cp.async double-buffered -----------------
// MODE 0: layer1 Wh  -> half2 store + f1/f2 dots (av = a_h slice)
// MODE 1: layer2 Wh2 -> fp32 store + g1/g2 dots  (av = a_o)
// MODE 2: fc1        -> elu(acc+bias) tf32 store, ld 256 (av = bias3 slice)
// MODE 3: fc2        -> acc+bias store cols<40, ld 40    (av = bias4)
#define SPAD 36
template<int NT, int KT, int MODE>
__global__ void __launch_bounds__(256) gat_mma_gemm(
        const float* __restrict__ A, int lda, const float* __restrict__ Bt,
        void* __restrict__ Cout, int M,
        const float* __restrict__ av, float* __restrict__ f1o, float* __restrict__ f2o) {
    constexpr int WARPS_M = (NT == 128) ? 4 : 8;
    constexpr int WM = 128 / WARPS_M;
    constexpr int MT = WM / 16;
    constexpr int ASZ = (MODE == 0) ? 256 : ((MODE == 3) ? 64 : 128);
    constexpr int AW = 128 * SPAD;
    constexpr int BW = NT * SPAD;
    constexpr int KTOT = KT * 32;

    extern __shared__ float smemf[];
    float*    s_a = smemf;
    uint32_t* As  = reinterpret_cast<uint32_t*>(smemf + ASZ);
    uint32_t* Bs  = As + 2 * AW;

    int tid = threadIdx.x, w = tid >> 5, l = tid & 31;
    int m0 = blockIdx.x * 128, n0 = blockIdx.y * NT;
    int wm = w % WARPS_M, wn = w / WARPS_M;
    int mbase = wm * WM, nbase = wn * 64;

    if (tid < ASZ) {
        int off = (MODE == 0) ? blockIdx.y * 256 : ((MODE == 2) ? blockIdx.y * 128 : 0);
        s_a[tid] = av[off + tid];
    }

    float acc[MT][8][4];
    #pragma unroll
    for (int i = 0; i < MT; i++)
        #pragma unroll
        for (int j = 0; j < 8; j++)
            #pragma unroll
            for (int q = 0; q < 4; q++) acc[i][j][q] = 0.f;

    int lq = l >> 2, lr = l & 3;

    auto issue = [&](int kt, int b) {
        int k0 = kt * 32;
        #pragma unroll
        for (int i = 0; i < 4; i++) {
            int f = tid + i * 256;
            int r = f >> 3, c4 = (f & 7) * 4;
            int m = m0 + r;
            bool p = m < M;
            const float* src = A + (size_t)(p ? m : 0) * lda + k0 + c4;
            cp16((uint32_t)__cvta_generic_to_shared(As + b * AW + r * SPAD + c4), src, p);
        }
        #pragma unroll
        for (int i = 0; i < NT / 32; i++) {
            int f = tid + i * 256;
            int r = f >> 3, c4 = (f & 7) * 4;
            const float* src = Bt + (size_t)(n0 + r) * KTOT + k0 + c4;
            cp16((uint32_t)__cvta_generic_to_shared(Bs + b * BW + r * SPAD + c4), src, true);
        }
    };

    issue(0, 0);
    CP_COMMIT();

    for (int kt = 0; kt < KT; kt++) {
        if (kt + 1 < KT) {
            issue(kt + 1, (kt + 1) & 1);
            CP_COMMIT();
            asm volatile("cp.async.wait_group 1;" ::: "memory");
        } else {
            asm volatile("cp.async.wait_group 0;" ::: "memory");
        }
        __syncthreads();

        int b = kt & 1;
        const uint32_t* Ab = As + b * AW;
        const uint32_t* Bb = Bs + b * BW;
        #pragma unroll
        for (int ks = 0; ks < 4; ks++) {
            int kc = ks * 8 + lr;
            uint32_t af[MT][4];
            #pragma unroll
            for (int mt = 0; mt < MT; mt++) {
                const uint32_t* ap = Ab + (mbase + mt * 16 + lq) * SPAD;
                af[mt][0] = ap[kc];
                af[mt][1] = ap[8 * SPAD + kc];
                af[mt][2] = ap[kc + 4];
                af[mt][3] = ap[8 * SPAD + kc + 4];
            }
            #pragma unroll
            for (int nt = 0; nt < 8; nt++) {
                const uint32_t* bp = Bb + (nbase + nt * 8 + lq) * SPAD;
                uint32_t b0 = bp[kc];
                uint32_t b1 = bp[kc + 4];
                #pragma unroll
                for (int mt = 0; mt < MT; mt++)
                    mma_tf32(acc[mt][nt][0], acc[mt][nt][1], acc[mt][nt][2], acc[mt][nt][3],
                             af[mt][0], af[mt][1], af[mt][2], af[mt][3], b0, b1);
            }
        }
        __syncthreads();
    }

    // epilogue stores
    #pragma unroll
    for (int mt = 0; mt < MT; mt++) {
        int r0 = m0 + mbase + mt * 16 + lq;
        int r1 = r0 + 8;
        #pragma unroll
        for (int nt = 0; nt < 8; nt++) {
            int lc = nbase + nt * 8 + lr * 2;   // tile-local col
            int c = n0 + lc;                    // global col
            if (MODE == 0) {
                __half2* Ch = reinterpret_cast<__half2*>(Cout);
                if (r0 < M) Ch[(size_t)r0 * 256 + (c >> 1)] =
                    __floats2half2_rn(acc[mt][nt][0], acc[mt][nt][1]);
                if (r1 < M) Ch[(size_t)r1 * 256 + (c >> 1)] =
                    __floats2half2_rn(acc[mt][nt][2], acc[mt][nt][3]);
            } else if (MODE == 1) {
                float* Cf = reinterpret_cast<float*>(Cout);
                if (r0 < M)
                    *reinterpret_cast<float2*>(Cf + (size_t)r0 * 64 + c) =
                        make_float2(acc[mt][nt][0], acc[mt][nt][1]);
                if (r1 < M)
                    *reinterpret_cast<float2*>(Cf + (size_t)r1 * 64 + c) =
                        make_float2(acc[mt][nt][2], acc[mt][nt][3]);
            } else if (MODE == 2) {
                float* Cf = reinterpret_cast<float*>(Cout);
                float bx = s_a[lc], by = s_a[lc + 1];
                if (r0 < M)
                    *reinterpret_cast<float2*>(Cf + (size_t)r0 * 256 + c) = make_float2(
                        __uint_as_float(f2tf32(elu1(acc[mt][nt][0] + bx))),
                        __uint_as_float(f2tf32(elu1(acc[mt][nt][1] + by))));
                if (r1 < M)
                    *reinterpret_cast<float2*>(Cf + (size_t)r1 * 256 + c) = make_float2(
                        __uint_as_float(f2tf32(elu1(acc[mt][nt][2] + bx))),
                        __uint_as_float(f2tf32(elu1(acc[mt][nt][3] + by))));
            } else {  // MODE 3
                if (c < NCLASS) {
                    float* Cf = reinterpret_cast<float*>(Cout);
                    float bx = s_a[c], by = s_a[c + 1];
                    if (r0 < M)
                        *reinterpret_cast<float2*>(Cf + (size_t)r0 * NCLASS + c) =
                            make_float2(acc[mt][nt][0] + bx, acc[mt][nt][1] + by);
                    if (r1 < M)
                        *reinterpret_cast<float2*>(Cf + (size_t)r1 * NCLASS + c) =
                            make_float2(acc[mt][nt][2] + bx, acc[mt][nt][3] + by);
                }
            }
        }
    }

    // fused attention-vector dots (layer GEMMs only)
    if (MODE <= 1) {
        const float* va = s_a + ((MODE == 0) ? wn * 128 : 0);
        float p1[MT][2] = {}, p2[MT][2] = {};
        #pragma unroll
        for (int nt = 0; nt < 8; nt++) {
            int o = nt * 8 + lr * 2;
            float a1x = va[o], a1y = va[o + 1];
            float a2x = va[64 + o], a2y = va[64 + o + 1];
            #pragma unroll
            for (int mt = 0; mt < MT; mt++) {
                p1[mt][0] += acc[mt][nt][0] * a1x + acc[mt][nt][1] * a1y;
                p2[mt][0] += acc[mt][nt][0] * a2x + acc[mt][nt][1] * a2y;
                p1[mt][1] += acc[mt][nt][2] * a1x + acc[mt][nt][3] * a1y;
                p2[mt][1] += acc[mt][nt][2] * a2x + acc[mt][nt][3] * a2y;
            }
        }
        #pragma unroll
        for (int mt = 0; mt < MT; mt++)
            #pragma unroll
            for (int rr = 0; rr < 2; rr++) {
                p1[mt][rr] += __shfl_xor_sync(0xffffffffu, p1[mt][rr], 1);
                p1[mt][rr] += __shfl_xor_sync(0xffffffffu, p1[mt][rr], 2);
                p2[mt][rr] += __shfl_xor_sync(0xffffffffu, p2[mt][rr], 1);
                p2[mt][rr] += __shfl_xor_sync(0xffffffffu, p2[mt][rr], 2);
            }
        if (lr == 0) {
            size_t hoff = (MODE == 0) ? (size_t)(blockIdx.y * 2 + wn) * NN : 0;
            #pragma unroll
            for (int mt = 0; mt < MT; mt++) {
                int r0 = m0 + mbase + mt * 16 + lq;
                int r1 = r0 + 8;
                if (r0 < M) { f1o[hoff + r0] = p1[mt][0]; f2o[hoff + r0] = p2[mt][0]; }
                if (r1 < M) { f1o[hoff + r1] = p1[mt][1]; f2o[hoff + r1] = p2[mt][1]; }
            }
        }
    }
}

// ---------------- K3: layer-1 sparse attention + aggregation + elu --------
__global__ void gat_agg1() {
    int n = blockIdx.x;
    __shared__ int   s_idx[MAXDEG];
    __shared__ int   s_off[MAXDEG];
    __shared__ float s_f2[NHEADS][MAXDEG];
    __shared__ float s_w [NHEADS][MAXDEG];
    int tid = threadIdx.x;
    int deg = d_cnt[n];

    for (int j = tid; j < deg; j += 256) {
        int c = d_nbr[n * MAXDEG + j];
        s_idx[j] = c;
        s_off[j] = c << 10;     // byte offset: c * 256 half2 * 4B
    }
    __syncthreads();
    for (int t = tid; t < deg * NHEADS; t += 256) {
        int h = t / deg, j = t - h * deg;
        s_f2[h][j] = d_f2[h * NN + s_idx[j]];
    }
    __syncthreads();

    int w = tid >> 5, lane = tid & 31;
    float f1v = d_f1[w * NN + n];

    float mx = -1e30f;
    for (int j = lane; j < deg; j += 32) mx = fmaxf(mx, leaky(f1v + s_f2[w][j]));
    #pragma unroll
    for (int off = 16; off; off >>= 1) mx = fmaxf(mx, __shfl_xor_sync(0xffffffffu, mx, off));

    float sum = 0.f;
    for (int j = lane; j < deg; j += 32) {
        float e = expf(leaky(f1v + s_f2[w][j]) - mx);
        s_w[w][j] = e;
        sum += e;
    }
    #pragma unroll
    for (int off = 16; off; off >>= 1) sum += __shfl_xor_sync(0xffffffffu, sum, off);
    __syncwarp();

    const char* base = reinterpret_cast<const char*>(d_Whh) + (size_t)(w * 32 + lane) * 4;
    float ax0 = 0.f, ay0 = 0.f, ax1 = 0.f, ay1 = 0.f;
    int j = 0;
    for (; j + 1 < deg; j += 2) {
        float w0 = s_w[w][j], w1 = s_w[w][j + 1];
        float2 v0 = __half22float2(*reinterpret_cast<const __half2*>(base + s_off[j]));
        float2 v1 = __half22float2(*reinterpret_cast<const __half2*>(base + s_off[j + 1]));
        ax0 += w0 * v0.x; ay0 += w0 * v0.y;
        ax1 += w1 * v1.x; ay1 += w1 * v1.y;
    }
    if (j < deg) {
        float w0 = s_w[w][j];
        float2 v0 = __half22float2(*reinterpret_cast<const __half2*>(base + s_off[j]));
        ax0 += w0 * v0.x; ay0 += w0 * v0.y;
    }
    float inv = 1.f / sum;
    uint2 o = make_uint2(f2tf32(elu1((ax0 + ax1) * inv)), f2tf32(elu1((ay0 + ay1) * inv)));
    reinterpret_cast<uint2*>(d_h1 + (size_t)n * 512 + w * 64)[lane] = o;
}

// ---------------- K6: layer-2 attention + aggregation (h2 only) -----------
__global__ void gat_agg2() {
    int n = blockIdx.x;
    __shared__ int   s_idx[MAXDEG];
    __shared__ float s_g2[MAXDEG];
    __shared__ float s_w [MAXDEG];
    __shared__ float s_sum;
    __shared__ float s_part[4][64];
    int tid = threadIdx.x;
    int deg = d_cnt[n];

    for (int j = tid; j < deg; j += 256) {
        int c = d_nbr[n * MAXDEG + j];
        s_idx[j] = c;
        s_g2[j]  = d_g2[c];
    }
    __syncthreads();

    if (tid < 32) {
        float g1n = d_g1[n];
        float mx = -1e30f;
        for (int j = tid; j < deg; j += 32) mx = fmaxf(mx, leaky(g1n + s_g2[j]));
        #pragma unroll
        for (int off = 16; off; off >>= 1) mx = fmaxf(mx, __shfl_xor_sync(0xffffffffu, mx, off));
        float sum = 0.f;
        for (int j = tid; j < deg; j += 32) {
            float e = expf(leaky(g1n + s_g2[j]) - mx);
            s_w[j] = e;
            sum += e;
        }
        #pragma unroll
        for (int off = 16; off; off >>= 1) sum += __shfl_xor_sync(0xffffffffu, sum, off);
        if (tid == 0) s_sum = sum;
    }
    __syncthreads();

    {
        int o = tid & 63, part = tid >> 6;
        float acc = 0.f;
        for (int j = part; j < deg; j += 4)
            acc += s_w[j] * d_Wh2[(size_t)s_idx[j] * 64 + o];
        s_part[part][o] = acc;
    }
    __syncthreads();
    if (tid < 64) {
        float h2 = (s_part[0][tid] + s_part[1][tid] + s_part[2][tid] + s_part[3][tid]) / s_sum;
        d_h2[(size_t)n * 64 + tid] = __uint_as_float(f2tf32(h2));
    }
}

// ---------------- launch ----------------------------------------------------
extern "C" void kernel_launch(void* const* d_in, const int* in_sizes, int n_in,
                              void* d_out, int out_size) {
    const float* x     = (const float*)d_in[0];
    const float* adj   = (const float*)d_in[1];
    const float* W_h   = (const float*)d_in[2];
    const float* a_h   = (const float*)d_in[3];
    const float* W_o   = (const float*)d_in[4];
    const float* a_o   = (const float*)d_in[5];
    const float* fc1_w = (const float*)d_in[6];
    const float* fc1_b = (const float*)d_in[7];
    const float* fc2_w = (const float*)d_in[8];
    const float* fc2_b = (const float*)d_in[9];
    float* out = (float*)d_out;

    void *pWhh, *pH1, *pXt, *pWh2, *pH2, *pH3, *pBt1, *pBt2, *pBt3, *pBt4;
    void *pB3, *pB4, *pF1, *pF2, *pG1, *pG2;
    cudaGetSymbolAddress(&pWhh, d_Whh);
    cudaGetSymbolAddress(&pH1,  d_h1);
    cudaGetSymbolAddress(&pXt,  d_xt);
    cudaGetSymbolAddress(&pWh2, d_Wh2);
    cudaGetSymbolAddress(&pH2,  d_h2);
    cudaGetSymbolAddress(&pH3,  d_h3);
    cudaGetSymbolAddress(&pBt1, d_Bt1);
    cudaGetSymbolAddress(&pBt2, d_Bt2);
    cudaGetSymbolAddress(&pBt3, d_Bt3);
    cudaGetSymbolAddress(&pBt4, d_Bt4);
    cudaGetSymbolAddress(&pB3,  d_bias3);
    cudaGetSymbolAddress(&pB4,  d_bias4);
    cudaGetSymbolAddress(&pF1,  d_f1);
    cudaGetSymbolAddress(&pF2,  d_f2);
    cudaGetSymbolAddress(&pG1,  d_g1);
    cudaGetSymbolAddress(&pG2,  d_g2);

    const int MB = (NN + 127) / 128;   // 40
    const int SM_M0 = (256 + 4 * 128 * SPAD) * 4;
    const int SM_M1 = (128 + 2 * 128 * SPAD + 2 * 64 * SPAD) * 4;
    const int SM_M2 = (128 + 4 * 128 * SPAD) * 4;
    const int SM_M3 = (64 + 2 * 128 * SPAD + 2 * 64 * SPAD) * 4;
    cudaFuncSetAttribute(gat_mma_gemm<128, 16, 0>, cudaFuncAttributeMaxDynamicSharedMemorySize, SM_M0);
    cudaFuncSetAttribute(gat_mma_gemm<64, 16, 1>,  cudaFuncAttributeMaxDynamicSharedMemorySize, SM_M1);
    cudaFuncSetAttribute(gat_mma_gemm<128, 2, 2>,  cudaFuncAttributeMaxDynamicSharedMemorySize, SM_M2);
    cudaFuncSetAttribute(gat_mma_gemm<64, 8, 3>,   cudaFuncAttributeMaxDynamicSharedMemorySize, SM_M3);

    cudaStream_t s2;
    cudaStreamCreateWithFlags(&s2, cudaStreamNonBlocking);
    cudaEvent_t e0, e1;
    cudaEventCreateWithFlags(&e0, cudaEventDisableTiming);
    cudaEventCreateWithFlags(&e1, cudaEventDisableTiming);

    cudaEventRecord(e0, 0);
    cudaStreamWaitEvent(s2, e0, 0);
    gat_build_csr<<<NN, 256, 0, s2>>>(adj);
    cudaEventRecord(e1, s2);

    gat_prep<<<PREP_BLOCKS, 256>>>(x, W_h, W_o, fc1_w, fc1_b, fc2_w, fc2_b);
    gat_mma_gemm<128, 16, 0><<<dim3(MB, 4), 256, SM_M0>>>((const float*)pXt, 512,
        (const float*)pBt1, pWhh, NN, a_h, (float*)pF1, (float*)pF2);
    cudaStreamWaitEvent(0, e1, 0);
    gat_agg1<<<NN, 256>>>();
    gat_mma_gemm<64, 16, 1><<<dim3(MB, 1), 256, SM_M1>>>((const float*)pH1, 512,
        (const float*)pBt2, pWh2, NN, a_o, (float*)pG1, (float*)pG2);
    gat_agg2<<<NN, 256>>>();
    gat_mma_gemm<128, 2, 2><<<dim3(MB, 2), 256, SM_M2>>>((const float*)pH2, 64,
        (const float*)pBt3, pH3, NN, (const float*)pB3, nullptr, nullptr);
    gat_mma_gemm<64, 8, 3><<<dim3(MB, 1), 256, SM_M3>>>((const float*)pH3, 256,
        (const float*)pBt4, out, NN, (const float*)pB4, nullptr, nullptr);

    cudaEventDestroy(e0);
    cudaEventDestroy(e1);
    cudaStreamDestroy(s2);
}

// round 8
// speedup vs baseline: 1.7490x; 1.0562x over previous
#include <cuda_runtime.h>
#include <cuda_fp16.h>
#include <math.h>
#include <cstdint>

#define NN 5000
#define NFEAT 512
#define NHID 64
#define NHEADS 8
#define NCLASS 40
#define LRALPHA 0.2f
#define MAXDEG 128

// ---------------- device scratch (no allocations allowed) ----------------
__device__ __half2 d_Whh[NN * 256];           // Wh as half2 [N, 256 pairs]
__device__ float d_h1 [NN * NHEADS * NHID];   // [N, 512] tf32 elu output
__device__ float d_Wh2[NN * NHID];            // [N, 64] fp32
__device__ float d_h2 [NN * NHID];            // [N, 64] tf32
__device__ float d_h3 [NN * 256];             // [N, 256] tf32 (200 used)
__device__ float d_Bt1[512 * 512];            // W_h^T  [n=h*64+o][k], tf32
__device__ float d_Bt2[64 * 512];             // W_o^T  [n][k], tf32
__device__ float d_Bt3[256 * 64];             // fc1_w^T padded [n][k], tf32
__device__ float d_Bt4[64 * 256];             // fc2_w^T padded [n][k], tf32
__device__ float d_bias3[256];
__device__ float d_bias4[64];
__device__ float d_f1 [NHEADS * NN];
__device__ float d_f2 [NHEADS * NN];
__device__ float d_g1 [NN];
__device__ float d_g2 [NN];
__device__ int   d_nbr[NN * MAXDEG];
__device__ int   d_cnt[NN];

__device__ __forceinline__ float leaky(float t) { return t > 0.f ? t : LRALPHA * t; }
__device__ __forceinline__ float elu1(float t)  { return t > 0.f ? t : expf(t) - 1.f; }
__device__ __forceinline__ uint32_t f2tf32(float f) {
    uint32_t u;
    asm("cvt.rna.tf32.f32 %0, %1;" : "=r"(u) : "f"(f));
    return u;
}
__device__ __forceinline__ void mma_tf32(float& c0, float& c1, float& c2, float& c3,
                                         uint32_t a0, uint32_t a1, uint32_t a2, uint32_t a3,
                                         uint32_t b0, uint32_t b1) {
    asm volatile("mma.sync.aligned.m16n8k8.row.col.f32.tf32.tf32.f32 "
                 "{%0,%1,%2,%3}, {%4,%5,%6,%7}, {%8,%9}, {%0,%1,%2,%3};"
                 : "+f"(c0), "+f"(c1), "+f"(c2), "+f"(c3)
                 : "r"(a0), "r"(a1), "r"(a2), "r"(a3), "r"(b0), "r"(b1));
}
__device__ __forceinline__ void cp16(uint32_t dst, const void* src, bool p) {
    int sz = p ? 16 : 0;
    asm volatile("cp.async.cg.shared.global [%0], [%1], 16, %2;"
                 :: "r"(dst), "l"(src), "r"(sz) : "memory");
}
#define CP_COMMIT() asm volatile("cp.async.commit_group;" ::: "memory")

// ---------------- K0: adjacency -> neighbor lists --------------------------
__global__ void gat_build_csr(const float* __restrict__ adj) {
    int n = blockIdx.x;
    __shared__ int cnt;
    if (threadIdx.x == 0) cnt = 0;
    __syncthreads();
    const float4* row = reinterpret_cast<const float4*>(adj + (size_t)n * NN);
    for (int i = threadIdx.x; i < NN / 4; i += blockDim.x) {
        float4 v = row[i];
        int c = i * 4;
        if (v.x != 0.f) { int p = atomicAdd(&cnt, 1); if (p < MAXDEG) d_nbr[n * MAXDEG + p] = c;     }
        if (v.y != 0.f) { int p = atomicAdd(&cnt, 1); if (p < MAXDEG) d_nbr[n * MAXDEG + p] = c + 1; }
        if (v.z != 0.f) { int p = atomicAdd(&cnt, 1); if (p < MAXDEG) d_nbr[n * MAXDEG + p] = c + 2; }
        if (v.w != 0.f) { int p = atomicAdd(&cnt, 1); if (p < MAXDEG) d_nbr[n * MAXDEG + p] = c + 3; }
    }
    __syncthreads();
    if (threadIdx.x == 0) d_cnt[n] = min(cnt, MAXDEG);
}

// ---------------- merged prep (weights only; x fed raw to HMMA) ------------
#define BT1_BLOCKS  (512 * 512 / 256)         // 1024
#define BT2_BLOCKS  (64 * 512 / 256)          // 128
#define BT3_BLOCKS  (256 * 64 / 256)          // 64
#define BT4_BLOCKS  (64 * 256 / 256)          // 64
#define PREP_BLOCKS (BT1_BLOCKS + BT2_BLOCKS + BT3_BLOCKS + BT4_BLOCKS + 1)
__global__ void gat_prep(const float* __restrict__ W_h, const float* __restrict__ W_o,
                         const float* __restrict__ fc1_w, const float* __restrict__ fc1_b,
                         const float* __restrict__ fc2_w, const float* __restrict__ fc2_b) {
    int b = blockIdx.x, tid = threadIdx.x;
    if (b < BT1_BLOCKS) {
        int idx = b * 256 + tid;
        int n = idx >> 9, k = idx & 511;
        int h = n >> 6, o = n & 63;
        d_Bt1[idx] = __uint_as_float(f2tf32(W_h[h * NFEAT * NHID + k * NHID + o]));
    } else if ((b -= BT1_BLOCKS) < BT2_BLOCKS) {
        int idx = b * 256 + tid;
        int n = idx >> 9, k = idx & 511;
        d_Bt2[idx] = __uint_as_float(f2tf32(W_o[k * NHID + n]));
    } else if ((b -= BT2_BLOCKS) < BT3_BLOCKS) {
        int idx = b * 256 + tid;
        int n = idx >> 6, k = idx & 63;
        d_Bt3[idx] = (n < 200) ? __uint_as_float(f2tf32(fc1_w[k * 200 + n])) : 0.f;
    } else if ((b -= BT3_BLOCKS) < BT4_BLOCKS) {
        int idx = b * 256 + tid;
        int n = idx >> 8, k = idx & 255;
        d_Bt4[idx] = (n < 40 && k < 200) ? __uint_as_float(f2tf32(fc2_w[k * 40 + n])) : 0.f;
    } else {
        d_bias3[tid] = (tid < 200) ? fc1_b[tid] : 0.f;
        if (tid < 64) d_bias4[tid] = (tid < 40) ? fc2_b[tid] : 0.f;
    }
}

// ---------------- tf32 HMMA GEMM, cp.async double-buffered -----------------
// MODE 0: layer1 Wh  -> half2 store + f1/f2 dots (av = a_h slice)
// MODE 1: layer2 Wh2 -> fp32 store + g1/g2 dots  (av = a_o)
// MODE 2: fc1        -> elu(acc+bias) tf32 store, ld 256 (av = bias3 slice)
// MODE 3: fc2        -> acc+bias store cols<40, ld 40    (av = bias4)
#define SPAD 36
template<int NT, int KT, int MODE>
__global__ void __launch_bounds__(256) gat_mma_gemm(
        const float* __restrict__ A, int lda, const float* __restrict__ Bt,
        void* __restrict__ Cout, int M,
        const float* __restrict__ av, float* __restrict__ f1o, float* __restrict__ f2o) {
    constexpr int WARPS_M = (NT == 128) ? 4 : 8;
    constexpr int WM = 128 / WARPS_M;
    constexpr int MT = WM / 16;
    constexpr int ASZ = (MODE == 0) ? 256 : ((MODE == 3) ? 64 : 128);
    constexpr int AW = 128 * SPAD;
    constexpr int BW = NT * SPAD;
    constexpr int KTOT = KT * 32;

    extern __shared__ float smemf[];
    float*    s_a = smemf;
    uint32_t* As  = reinterpret_cast<uint32_t*>(smemf + ASZ);
    uint32_t* Bs  = As + 2 * AW;

    int tid = threadIdx.x, w = tid >> 5, l = tid & 31;
    int m0 = blockIdx.x * 128, n0 = blockIdx.y * NT;
    int wm = w % WARPS_M, wn = w / WARPS_M;
    int mbase = wm * WM, nbase = wn * 64;

    if (tid < ASZ) {
        int off = (MODE == 0) ? blockIdx.y * 256 : ((MODE == 2) ? blockIdx.y * 128 : 0);
        s_a[tid] = av[off + tid];
    }

    float acc[MT][8][4];
    #pragma unroll
    for (int i = 0; i < MT; i++)
        #pragma unroll
        for (int j = 0; j < 8; j++)
            #pragma unroll
            for (int q = 0; q < 4; q++) acc[i][j][q] = 0.f;

    int lq = l >> 2, lr = l & 3;

    auto issue = [&](int kt, int b) {
        int k0 = kt * 32;
        #pragma unroll
        for (int i = 0; i < 4; i++) {
            int f = tid + i * 256;
            int r = f >> 3, c4 = (f & 7) * 4;
            int m = m0 + r;
            bool p = m < M;
            const float* src = A + (size_t)(p ? m : 0) * lda + k0 + c4;
            cp16((uint32_t)__cvta_generic_to_shared(As + b * AW + r * SPAD + c4), src, p);
        }
        #pragma unroll
        for (int i = 0; i < NT / 32; i++) {
            int f = tid + i * 256;
            int r = f >> 3, c4 = (f & 7) * 4;
            const float* src = Bt + (size_t)(n0 + r) * KTOT + k0 + c4;
            cp16((uint32_t)__cvta_generic_to_shared(Bs + b * BW + r * SPAD + c4), src, true);
        }
    };

    issue(0, 0);
    CP_COMMIT();

    for (int kt = 0; kt < KT; kt++) {
        if (kt + 1 < KT) {
            issue(kt + 1, (kt + 1) & 1);
            CP_COMMIT();
            asm volatile("cp.async.wait_group 1;" ::: "memory");
        } else {
            asm volatile("cp.async.wait_group 0;" ::: "memory");
        }
        __syncthreads();

        int b = kt & 1;
        const uint32_t* Ab = As + b * AW;
        const uint32_t* Bb = Bs + b * BW;
        #pragma unroll
        for (int ks = 0; ks < 4; ks++) {
            int kc = ks * 8 + lr;
            uint32_t af[MT][4];
            #pragma unroll
            for (int mt = 0; mt < MT; mt++) {
                const uint32_t* ap = Ab + (mbase + mt * 16 + lq) * SPAD;
                af[mt][0] = ap[kc];
                af[mt][1] = ap[8 * SPAD + kc];
                af[mt][2] = ap[kc + 4];
                af[mt][3] = ap[8 * SPAD + kc + 4];
            }
            #pragma unroll
            for (int nt = 0; nt < 8; nt++) {
                const uint32_t* bp = Bb + (nbase + nt * 8 + lq) * SPAD;
                uint32_t b0 = bp[kc];
                uint32_t b1 = bp[kc + 4];
                #pragma unroll
                for (int mt = 0; mt < MT; mt++)
                    mma_tf32(acc[mt][nt][0], acc[mt][nt][1], acc[mt][nt][2], acc[mt][nt][3],
                             af[mt][0], af[mt][1], af[mt][2], af[mt][3], b0, b1);
            }
        }
        __syncthreads();
    }

    // epilogue stores
    #pragma unroll
    for (int mt = 0; mt < MT; mt++) {
        int r0 = m0 + mbase + mt * 16 + lq;
        int r1 = r0 + 8;
        #pragma unroll
        for (int nt = 0; nt < 8; nt++) {
            int lc = nbase + nt * 8 + lr * 2;   // tile-local col
            int c = n0 + lc;                    // global col
            if (MODE == 0) {
                __half2* Ch = reinterpret_cast<__half2*>(Cout);
                if (r0 < M) Ch[(size_t)r0 * 256 + (c >> 1)] =
                    __floats2half2_rn(acc[mt][nt][0], acc[mt][nt][1]);
                if (r1 < M) Ch[(size_t)r1 * 256 + (c >> 1)] =
                    __floats2half2_rn(acc[mt][nt][2], acc[mt][nt][3]);
            } else if (MODE == 1) {
                float* Cf = reinterpret_cast<float*>(Cout);
                if (r0 < M)
                    *reinterpret_cast<float2*>(Cf + (size_t)r0 * 64 + c) =
                        make_float2(acc[mt][nt][0], acc[mt][nt][1]);
                if (r1 < M)
                    *reinterpret_cast<float2*>(Cf + (size_t)r1 * 64 + c) =
                        make_float2(acc[mt][nt][2], acc[mt][nt][3]);
            } else if (MODE == 2) {
                float* Cf = reinterpret_cast<float*>(Cout);
                float bx = s_a[lc], by = s_a[lc + 1];
                if (r0 < M)
                    *reinterpret_cast<float2*>(Cf + (size_t)r0 * 256 + c) = make_float2(
                        __uint_as_float(f2tf32(elu1(acc[mt][nt][0] + bx))),
                        __uint_as_float(f2tf32(elu1(acc[mt][nt][1] + by))));
                if (r1 < M)
                    *reinterpret_cast<float2*>(Cf + (size_t)r1 * 256 + c) = make_float2(
                        __uint_as_float(f2tf32(elu1(acc[mt][nt][2] + bx))),
                        __uint_as_float(f2tf32(elu1(acc[mt][nt][3] + by))));
            } else {  // MODE 3
                if (c < NCLASS) {
                    float* Cf = reinterpret_cast<float*>(Cout);
                    float bx = s_a[c], by = s_a[c + 1];
                    if (r0 < M)
                        *reinterpret_cast<float2*>(Cf + (size_t)r0 * NCLASS + c) =
                            make_float2(acc[mt][nt][0] + bx, acc[mt][nt][1] + by);
                    if (r1 < M)
                        *reinterpret_cast<float2*>(Cf + (size_t)r1 * NCLASS + c) =
                            make_float2(acc[mt][nt][2] + bx, acc[mt][nt][3] + by);
                }
            }
        }
    }

    // fused attention-vector dots (layer GEMMs only)
    if (MODE <= 1) {
        const float* va = s_a + ((MODE == 0) ? wn * 128 : 0);
        float p1[MT][2] = {}, p2[MT][2] = {};
        #pragma unroll
        for (int nt = 0; nt < 8; nt++) {
            int o = nt * 8 + lr * 2;
            float a1x = va[o], a1y = va[o + 1];
            float a2x = va[64 + o], a2y = va[64 + o + 1];
            #pragma unroll
            for (int mt = 0; mt < MT; mt++) {
                p1[mt][0] += acc[mt][nt][0] * a1x + acc[mt][nt][1] * a1y;
                p2[mt][0] += acc[mt][nt][0] * a2x + acc[mt][nt][1] * a2y;
                p1[mt][1] += acc[mt][nt][2] * a1x + acc[mt][nt][3] * a1y;
                p2[mt][1] += acc[mt][nt][2] * a2x + acc[mt][nt][3] * a2y;
            }
        }
        #pragma unroll
        for (int mt = 0; mt < MT; mt++)
            #pragma unroll
            for (int rr = 0; rr < 2; rr++) {
                p1[mt][rr] += __shfl_xor_sync(0xffffffffu, p1[mt][rr], 1);
                p1[mt][rr] += __shfl_xor_sync(0xffffffffu, p1[mt][rr], 2);
                p2[mt][rr] += __shfl_xor_sync(0xffffffffu, p2[mt][rr], 1);
                p2[mt][rr] += __shfl_xor_sync(0xffffffffu, p2[mt][rr], 2);
            }
        if (lr == 0) {
            size_t hoff = (MODE == 0) ? (size_t)(blockIdx.y * 2 + wn) * NN : 0;
            #pragma unroll
            for (int mt = 0; mt < MT; mt++) {
                int r0 = m0 + mbase + mt * 16 + lq;
                int r1 = r0 + 8;
                if (r0 < M) { f1o[hoff + r0] = p1[mt][0]; f2o[hoff + r0] = p2[mt][0]; }
                if (r1 < M) { f1o[hoff + r1] = p1[mt][1]; f2o[hoff + r1] = p2[mt][1]; }
            }
        }
    }
}

// ---------------- K3: layer-1 sparse attention + aggregation + elu --------
__global__ void gat_agg1() {
    int n = blockIdx.x;
    __shared__ int   s_idx[MAXDEG];
    __shared__ float s_f2[NHEADS][MAXDEG];
    __shared__ float s_w [NHEADS][MAXDEG];
    int tid = threadIdx.x;
    int deg = d_cnt[n];

    for (int j = tid; j < deg; j += 256) s_idx[j] = d_nbr[n * MAXDEG + j];
    __syncthreads();
    for (int t = tid; t < deg * NHEADS; t += 256) {
        int h = t / deg, j = t - h * deg;
        s_f2[h][j] = d_f2[h * NN + s_idx[j]];
    }
    __syncthreads();

    int w = tid >> 5, lane = tid & 31;
    float f1v = d_f1[w * NN + n];

    float mx = -1e30f;
    for (int j = lane; j < deg; j += 32) mx = fmaxf(mx, leaky(f1v + s_f2[w][j]));
    #pragma unroll
    for (int off = 16; off; off >>= 1) mx = fmaxf(mx, __shfl_xor_sync(0xffffffffu, mx, off));

    float sum = 0.f;
    for (int j = lane; j < deg; j += 32) {
        float e = expf(leaky(f1v + s_f2[w][j]) - mx);
        s_w[w][j] = e;
        sum += e;
    }
    #pragma unroll
    for (int off = 16; off; off >>= 1) sum += __shfl_xor_sync(0xffffffffu, sum, off);
    __syncwarp();

    float accx = 0.f, accy = 0.f;
    const __half2* whb = d_Whh + w * 32 + lane;
    for (int j = 0; j < deg; j++) {
        float wj = s_w[w][j];
        float2 v = __half22float2(whb[(size_t)s_idx[j] * 256]);
        accx += wj * v.x;
        accy += wj * v.y;
    }
    float inv = 1.f / sum;
    uint2 o = make_uint2(f2tf32(elu1(accx * inv)), f2tf32(elu1(accy * inv)));
    reinterpret_cast<uint2*>(d_h1 + (size_t)n * 512 + w * 64)[lane] = o;
}

// ---------------- K6: layer-2 attention + aggregation (h2 only) -----------
__global__ void gat_agg2() {
    int n = blockIdx.x;
    __shared__ int   s_idx[MAXDEG];
    __shared__ float s_g2[MAXDEG];
    __shared__ float s_w [MAXDEG];
    __shared__ float s_sum;
    __shared__ float s_part[4][64];
    int tid = threadIdx.x;
    int deg = d_cnt[n];

    for (int j = tid; j < deg; j += 256) {
        int c = d_nbr[n * MAXDEG + j];
        s_idx[j] = c;
        s_g2[j]  = d_g2[c];
    }
    __syncthreads();

    if (tid < 32) {
        float g1n = d_g1[n];
        float mx = -1e30f;
        for (int j = tid; j < deg; j += 32) mx = fmaxf(mx, leaky(g1n + s_g2[j]));
        #pragma unroll
        for (int off = 16; off; off >>= 1) mx = fmaxf(mx, __shfl_xor_sync(0xffffffffu, mx, off));
        float sum = 0.f;
        for (int j = tid; j < deg; j += 32) {
            float e = expf(leaky(g1n + s_g2[j]) - mx);
            s_w[j] = e;
            sum += e;
        }
        #pragma unroll
        for (int off = 16; off; off >>= 1) sum += __shfl_xor_sync(0xffffffffu, sum, off);
        if (tid == 0) s_sum = sum;
    }
    __syncthreads();

    {
        int o = tid & 63, part = tid >> 6;
        float acc = 0.f;
        for (int j = part; j < deg; j += 4)
            acc += s_w[j] * d_Wh2[(size_t)s_idx[j] * 64 + o];
        s_part[part][o] = acc;
    }
    __syncthreads();
    if (tid < 64) {
        float h2 = (s_part[0][tid] + s_part[1][tid] + s_part[2][tid] + s_part[3][tid]) / s_sum;
        d_h2[(size_t)n * 64 + tid] = __uint_as_float(f2tf32(h2));
    }
}

// ---------------- launch ----------------------------------------------------
extern "C" void kernel_launch(void* const* d_in, const int* in_sizes, int n_in,
                              void* d_out, int out_size) {
    const float* x     = (const float*)d_in[0];
    const float* adj   = (const float*)d_in[1];
    const float* W_h   = (const float*)d_in[2];
    const float* a_h   = (const float*)d_in[3];
    const float* W_o   = (const float*)d_in[4];
    const float* a_o   = (const float*)d_in[5];
    const float* fc1_w = (const float*)d_in[6];
    const float* fc1_b = (const float*)d_in[7];
    const float* fc2_w = (const float*)d_in[8];
    const float* fc2_b = (const float*)d_in[9];
    float* out = (float*)d_out;

    void *pWhh, *pH1, *pWh2, *pH2, *pH3, *pBt1, *pBt2, *pBt3, *pBt4;
    void *pB3, *pB4, *pF1, *pF2, *pG1, *pG2;
    cudaGetSymbolAddress(&pWhh, d_Whh);
    cudaGetSymbolAddress(&pH1,  d_h1);
    cudaGetSymbolAddress(&pWh2, d_Wh2);
    cudaGetSymbolAddress(&pH2,  d_h2);
    cudaGetSymbolAddress(&pH3,  d_h3);
    cudaGetSymbolAddress(&pBt1, d_Bt1);
    cudaGetSymbolAddress(&pBt2, d_Bt2);
    cudaGetSymbolAddress(&pBt3, d_Bt3);
    cudaGetSymbolAddress(&pBt4, d_Bt4);
    cudaGetSymbolAddress(&pB3,  d_bias3);
    cudaGetSymbolAddress(&pB4,  d_bias4);
    cudaGetSymbolAddress(&pF1,  d_f1);
    cudaGetSymbolAddress(&pF2,  d_f2);
    cudaGetSymbolAddress(&pG1,  d_g1);
    cudaGetSymbolAddress(&pG2,  d_g2);

    const int MB = (NN + 127) / 128;   // 40
    const int SM_M0 = (256 + 4 * 128 * SPAD) * 4;
    const int SM_M1 = (128 + 2 * 128 * SPAD + 2 * 64 * SPAD) * 4;
    const int SM_M2 = (128 + 4 * 128 * SPAD) * 4;
    const int SM_M3 = (64 + 2 * 128 * SPAD + 2 * 64 * SPAD) * 4;
    cudaFuncSetAttribute(gat_mma_gemm<128, 16, 0>, cudaFuncAttributeMaxDynamicSharedMemorySize, SM_M0);
    cudaFuncSetAttribute(gat_mma_gemm<64, 16, 1>,  cudaFuncAttributeMaxDynamicSharedMemorySize, SM_M1);
    cudaFuncSetAttribute(gat_mma_gemm<128, 2, 2>,  cudaFuncAttributeMaxDynamicSharedMemorySize, SM_M2);
    cudaFuncSetAttribute(gat_mma_gemm<64, 8, 3>,   cudaFuncAttributeMaxDynamicSharedMemorySize, SM_M3);

    cudaStream_t s2;
    cudaStreamCreateWithFlags(&s2, cudaStreamNonBlocking);
    cudaEvent_t e0, e1;
    cudaEventCreateWithFlags(&e0, cudaEventDisableTiming);
    cudaEventCreateWithFlags(&e1, cudaEventDisableTiming);

    cudaEventRecord(e0, 0);
    cudaStreamWaitEvent(s2, e0, 0);
    gat_build_csr<<<NN, 256, 0, s2>>>(adj);
    cudaEventRecord(e1, s2);

    gat_prep<<<PREP_BLOCKS, 256>>>(W_h, W_o, fc1_w, fc1_b, fc2_w, fc2_b);
    gat_mma_gemm<128, 16, 0><<<dim3(MB, 4), 256, SM_M0>>>(x, 512,
        (const float*)pBt1, pWhh, NN, a_h, (float*)pF1, (float*)pF2);
    cudaStreamWaitEvent(0, e1, 0);
    gat_agg1<<<NN, 256>>>();
    gat_mma_gemm<64, 16, 1><<<dim3(MB, 1), 256, SM_M1>>>((const float*)pH1, 512,
        (const float*)pBt2, pWh2, NN, a_o, (float*)pG1, (float*)pG2);
    gat_agg2<<<NN, 256>>>();
    gat_mma_gemm<128, 2, 2><<<dim3(MB, 2), 256, SM_M2>>>((const float*)pH2, 64,
        (const float*)pBt3, pH3, NN, (const float*)pB3, nullptr, nullptr);
    gat_mma_gemm<64, 8, 3><<<dim3(MB, 1), 256, SM_M3>>>((const float*)pH3, 256,
        (const float*)pBt4, out, NN, (const float*)pB4, nullptr, nullptr);

    cudaEventDestroy(e0);
    cudaEventDestroy(e1);
    cudaStreamDestroy(s2);
}

// round 9
// speedup vs baseline: 1.8541x; 1.0601x over previous
#include <cuda_runtime.h>
#include <cuda_fp16.h>
#include <math.h>
#include <cstdint>

#define NN 5000
#define NFEAT 512
#define NHID 64
#define NHEADS 8
#define NCLASS 40
#define LRALPHA 0.2f
#define MAXDEG 128

// ---------------- device scratch (no allocations allowed) ----------------
__device__ __half2 d_Whh[NN * 256];           // Wh as half2 [N, 256 pairs]
__device__ float d_h1 [NN * NHEADS * NHID];   // [N, 512] tf32 elu output
__device__ float d_Wh2[NN * NHID];            // [N, 64] fp32
__device__ float d_h2 [NN * NHID];            // [N, 64] tf32
__device__ float d_h3 [NN * 256];             // [N, 256] tf32 (200 used)
__device__ float d_Bt1[512 * 512];            // W_h^T  [n=h*64+o][k], tf32
__device__ float d_Bt2[64 * 512];             // W_o^T  [n][k], tf32
__device__ float d_Bt3[256 * 64];             // fc1_w^T padded [n][k], tf32
__device__ float d_Bt4[64 * 256];             // fc2_w^T padded [n][k], tf32
__device__ float d_bias3[256];
__device__ float d_bias4[64];
__device__ float d_f1 [NHEADS * NN];
__device__ float d_f2 [NHEADS * NN];
__device__ float d_g1 [NN];
__device__ float d_g2 [NN];
__device__ int   d_nbr[NN * MAXDEG];
__device__ int   d_cnt[NN];

__device__ __forceinline__ float leaky(float t) { return t > 0.f ? t : LRALPHA * t; }
__device__ __forceinline__ float elu1(float t)  { return t > 0.f ? t : expf(t) - 1.f; }
__device__ __forceinline__ uint32_t f2tf32(float f) {
    uint32_t u;
    asm("cvt.rna.tf32.f32 %0, %1;" : "=r"(u) : "f"(f));
    return u;
}
__device__ __forceinline__ void mma_tf32(float& c0, float& c1, float& c2, float& c3,
                                         uint32_t a0, uint32_t a1, uint32_t a2, uint32_t a3,
                                         uint32_t b0, uint32_t b1) {
    asm volatile("mma.sync.aligned.m16n8k8.row.col.f32.tf32.tf32.f32 "
                 "{%0,%1,%2,%3}, {%4,%5,%6,%7}, {%8,%9}, {%0,%1,%2,%3};"
                 : "+f"(c0), "+f"(c1), "+f"(c2), "+f"(c3)
                 : "r"(a0), "r"(a1), "r"(a2), "r"(a3), "r"(b0), "r"(b1));
}
__device__ __forceinline__ void cp16(uint32_t dst, const void* src, bool p) {
    int sz = p ? 16 : 0;
    asm volatile("cp.async.cg.shared.global [%0], [%1], 16, %2;"
                 :: "r"(dst), "l"(src), "r"(sz) : "memory");
}
#define CP_COMMIT() asm volatile("cp.async.commit_group;" ::: "memory")

// ---------------- K0: adjacency -> neighbor lists --------------------------
__global__ void gat_build_csr(const float* __restrict__ adj) {
    int n = blockIdx.x;
    __shared__ int cnt;
    if (threadIdx.x == 0) cnt = 0;
    __syncthreads();
    const float4* row = reinterpret_cast<const float4*>(adj + (size_t)n * NN);
    for (int i = threadIdx.x; i < NN / 4; i += blockDim.x) {
        float4 v = row[i];
        int c = i * 4;
        if (v.x != 0.f) { int p = atomicAdd(&cnt, 1); if (p < MAXDEG) d_nbr[n * MAXDEG + p] = c;     }
        if (v.y != 0.f) { int p = atomicAdd(&cnt, 1); if (p < MAXDEG) d_nbr[n * MAXDEG + p] = c + 1; }
        if (v.z != 0.f) { int p = atomicAdd(&cnt, 1); if (p < MAXDEG) d_nbr[n * MAXDEG + p] = c + 2; }
        if (v.w != 0.f) { int p = atomicAdd(&cnt, 1); if (p < MAXDEG) d_nbr[n * MAXDEG + p] = c + 3; }
    }
    __syncthreads();
    if (threadIdx.x == 0) d_cnt[n] = min(cnt, MAXDEG);
}

// ---------------- merged prep (weights only; x fed raw to HMMA) ------------
#define BT1_BLOCKS  (512 * 512 / 256)         // 1024
#define BT2_BLOCKS  (64 * 512 / 256)          // 128
#define BT3_BLOCKS  (256 * 64 / 256)          // 64
#define BT4_BLOCKS  (64 * 256 / 256)          // 64
#define PREP_BLOCKS (BT1_BLOCKS + BT2_BLOCKS + BT3_BLOCKS + BT4_BLOCKS + 1)
__global__ void gat_prep(const float* __restrict__ W_h, const float* __restrict__ W_o,
                         const float* __restrict__ fc1_w, const float* __restrict__ fc1_b,
                         const float* __restrict__ fc2_w, const float* __restrict__ fc2_b) {
    int b = blockIdx.x, tid = threadIdx.x;
    if (b < BT1_BLOCKS) {
        int idx = b * 256 + tid;
        int n = idx >> 9, k = idx & 511;
        int h = n >> 6, o = n & 63;
        d_Bt1[idx] = __uint_as_float(f2tf32(W_h[h * NFEAT * NHID + k * NHID + o]));
    } else if ((b -= BT1_BLOCKS) < BT2_BLOCKS) {
        int idx = b * 256 + tid;
        int n = idx >> 9, k = idx & 511;
        d_Bt2[idx] = __uint_as_float(f2tf32(W_o[k * NHID + n]));
    } else if ((b -= BT2_BLOCKS) < BT3_BLOCKS) {
        int idx = b * 256 + tid;
        int n = idx >> 6, k = idx & 63;
        d_Bt3[idx] = (n < 200) ? __uint_as_float(f2tf32(fc1_w[k * 200 + n])) : 0.f;
    } else if ((b -= BT3_BLOCKS) < BT4_BLOCKS) {
        int idx = b * 256 + tid;
        int n = idx >> 8, k = idx & 255;
        d_Bt4[idx] = (n < 40 && k < 200) ? __uint_as_float(f2tf32(fc2_w[k * 40 + n])) : 0.f;
    } else {
        d_bias3[tid] = (tid < 200) ? fc1_b[tid] : 0.f;
        if (tid < 64) d_bias4[tid] = (tid < 40) ? fc2_b[tid] : 0.f;
    }
}

// ---------------- tf32 HMMA GEMM, 64-row tiles, cp.async double-buffered ---
// 8 warps: 4 m-warps x 2 n-warps; warp tile 16 x (NT/2).
// MODE 0: layer1 Wh  -> half2 store + f1/f2 dots (av = a_h slice)
// MODE 1: layer2 Wh2 -> fp32 store + g1/g2 dots (cross-warp smem reduce)
// MODE 2: fc1        -> elu(acc+bias) tf32 store (av = bias3 slice)
// MODE 3: fc2        -> acc+bias store cols<40   (av = bias4)
#define SPAD 36
template<int NT, int KT, int MODE>
__global__ void __launch_bounds__(256) gat_mma_gemm(
        const float* __restrict__ A, int lda, const float* __restrict__ Bt,
        void* __restrict__ Cout, int M,
        const float* __restrict__ av, float* __restrict__ f1o, float* __restrict__ f2o) {
    constexpr int WNT = NT / 2;            // per-warp n width
    constexpr int NTI = WNT / 8;           // nt iterations per warp
    constexpr int ASZ = (MODE == 0) ? 256 : ((MODE == 3) ? 64 : 128);
    constexpr int AW = 64 * SPAD;
    constexpr int BW = NT * SPAD;
    constexpr int KTOT = KT * 32;

    extern __shared__ float smemf[];
    float*    s_a   = smemf;
    float*    s_red = smemf + ASZ;          // [2][2][64] for MODE1
    uint32_t* As    = reinterpret_cast<uint32_t*>(s_red + 256);
    uint32_t* Bs    = As + 2 * AW;

    int tid = threadIdx.x, w = tid >> 5, l = tid & 31;
    int m0 = blockIdx.x * 64, n0 = blockIdx.y * NT;
    int wm = w & 3, wn = w >> 2;
    int mbase = wm * 16, nbase = wn * WNT;

    if (tid < ASZ) {
        int off = (MODE == 0) ? blockIdx.y * 256 : ((MODE == 2) ? blockIdx.y * 128 : 0);
        s_a[tid] = av[off + tid];
    }

    float acc[NTI][4];
    #pragma unroll
    for (int j = 0; j < NTI; j++)
        #pragma unroll
        for (int q = 0; q < 4; q++) acc[j][q] = 0.f;

    int lq = l >> 2, lr = l & 3;

    auto issue = [&](int kt, int b) {
        int k0 = kt * 32;
        #pragma unroll
        for (int i = 0; i < 2; i++) {
            int f = tid + i * 256;
            int r = f >> 3, c4 = (f & 7) * 4;
            int m = m0 + r;
            bool p = m < M;
            const float* src = A + (size_t)(p ? m : 0) * lda + k0 + c4;
            cp16((uint32_t)__cvta_generic_to_shared(As + b * AW + r * SPAD + c4), src, p);
        }
        #pragma unroll
        for (int i = 0; i < NT / 32; i++) {
            int f = tid + i * 256;
            int r = f >> 3, c4 = (f & 7) * 4;
            const float* src = Bt + (size_t)(n0 + r) * KTOT + k0 + c4;
            cp16((uint32_t)__cvta_generic_to_shared(Bs + b * BW + r * SPAD + c4), src, true);
        }
    };

    issue(0, 0);
    CP_COMMIT();

    for (int kt = 0; kt < KT; kt++) {
        if (kt + 1 < KT) {
            issue(kt + 1, (kt + 1) & 1);
            CP_COMMIT();
            asm volatile("cp.async.wait_group 1;" ::: "memory");
        } else {
            asm volatile("cp.async.wait_group 0;" ::: "memory");
        }
        __syncthreads();

        int b = kt & 1;
        const uint32_t* Ab = As + b * AW;
        const uint32_t* Bb = Bs + b * BW;
        #pragma unroll
        for (int ks = 0; ks < 4; ks++) {
            int kc = ks * 8 + lr;
            const uint32_t* ap = Ab + (mbase + lq) * SPAD;
            uint32_t a0 = ap[kc];
            uint32_t a1 = ap[8 * SPAD + kc];
            uint32_t a2 = ap[kc + 4];
            uint32_t a3 = ap[8 * SPAD + kc + 4];
            #pragma unroll
            for (int nt = 0; nt < NTI; nt++) {
                const uint32_t* bp = Bb + (nbase + nt * 8 + lq) * SPAD;
                uint32_t b0 = bp[kc];
                uint32_t b1 = bp[kc + 4];
                mma_tf32(acc[nt][0], acc[nt][1], acc[nt][2], acc[nt][3],
                         a0, a1, a2, a3, b0, b1);
            }
        }
        __syncthreads();
    }

    // epilogue stores
    int r0 = m0 + mbase + lq;
    int r1 = r0 + 8;
    #pragma unroll
    for (int nt = 0; nt < NTI; nt++) {
        int lc = nbase + nt * 8 + lr * 2;   // tile-local col
        int c = n0 + lc;                    // global col
        if (MODE == 0) {
            __half2* Ch = reinterpret_cast<__half2*>(Cout);
            if (r0 < M) Ch[(size_t)r0 * 256 + (c >> 1)] =
                __floats2half2_rn(acc[nt][0], acc[nt][1]);
            if (r1 < M) Ch[(size_t)r1 * 256 + (c >> 1)] =
                __floats2half2_rn(acc[nt][2], acc[nt][3]);
        } else if (MODE == 1) {
            float* Cf = reinterpret_cast<float*>(Cout);
            if (r0 < M)
                *reinterpret_cast<float2*>(Cf + (size_t)r0 * 64 + c) =
                    make_float2(acc[nt][0], acc[nt][1]);
            if (r1 < M)
                *reinterpret_cast<float2*>(Cf + (size_t)r1 * 64 + c) =
                    make_float2(acc[nt][2], acc[nt][3]);
        } else if (MODE == 2) {
            float* Cf = reinterpret_cast<float*>(Cout);
            float bx = s_a[lc], by = s_a[lc + 1];
            if (r0 < M)
                *reinterpret_cast<float2*>(Cf + (size_t)r0 * 256 + c) = make_float2(
                    __uint_as_float(f2tf32(elu1(acc[nt][0] + bx))),
                    __uint_as_float(f2tf32(elu1(acc[nt][1] + by))));
            if (r1 < M)
                *reinterpret_cast<float2*>(Cf + (size_t)r1 * 256 + c) = make_float2(
                    __uint_as_float(f2tf32(elu1(acc[nt][2] + bx))),
                    __uint_as_float(f2tf32(elu1(acc[nt][3] + by))));
        } else {  // MODE 3
            if (c < NCLASS) {
                float* Cf = reinterpret_cast<float*>(Cout);
                float bx = s_a[c], by = s_a[c + 1];
                if (r0 < M)
                    *reinterpret_cast<float2*>(Cf + (size_t)r0 * NCLASS + c) =
                        make_float2(acc[nt][0] + bx, acc[nt][1] + by);
                if (r1 < M)
                    *reinterpret_cast<float2*>(Cf + (size_t)r1 * NCLASS + c) =
                        make_float2(acc[nt][2] + bx, acc[nt][3] + by);
            }
        }
    }

    // fused attention-vector dots
    if (MODE <= 1) {
        const float* va = (MODE == 0) ? s_a + wn * 128 : s_a;
        float p1a = 0.f, p1b = 0.f, p2a = 0.f, p2b = 0.f;
        #pragma unroll
        for (int nt = 0; nt < NTI; nt++) {
            int o = (MODE == 0) ? (nt * 8 + lr * 2) : (nbase + nt * 8 + lr * 2);
            float a1x = va[o], a1y = va[o + 1];
            float a2x = va[64 + o], a2y = va[64 + o + 1];
            p1a += acc[nt][0] * a1x + acc[nt][1] * a1y;
            p2a += acc[nt][0] * a2x + acc[nt][1] * a2y;
            p1b += acc[nt][2] * a1x + acc[nt][3] * a1y;
            p2b += acc[nt][2] * a2x + acc[nt][3] * a2y;
        }
        p1a += __shfl_xor_sync(0xffffffffu, p1a, 1); p1a += __shfl_xor_sync(0xffffffffu, p1a, 2);
        p1b += __shfl_xor_sync(0xffffffffu, p1b, 1); p1b += __shfl_xor_sync(0xffffffffu, p1b, 2);
        p2a += __shfl_xor_sync(0xffffffffu, p2a, 1); p2a += __shfl_xor_sync(0xffffffffu, p2a, 2);
        p2b += __shfl_xor_sync(0xffffffffu, p2b, 1); p2b += __shfl_xor_sync(0xffffffffu, p2b, 2);
        if (MODE == 0) {
            if (lr == 0) {
                size_t hoff = (size_t)(blockIdx.y * 2 + wn) * NN;
                if (r0 < M) { f1o[hoff + r0] = p1a; f2o[hoff + r0] = p2a; }
                if (r1 < M) { f1o[hoff + r1] = p1b; f2o[hoff + r1] = p2b; }
            }
        } else {
            // cross-warp (wn) partial reduce via smem
            float* sp1 = s_red;            // [2][64]
            float* sp2 = s_red + 128;      // [2][64]
            if (lr == 0) {
                sp1[wn * 64 + mbase + lq] = p1a;
                sp1[wn * 64 + mbase + lq + 8] = p1b;
                sp2[wn * 64 + mbase + lq] = p2a;
                sp2[wn * 64 + mbase + lq + 8] = p2b;
            }
            __syncthreads();
            if (tid < 64 && m0 + tid < M) {
                f1o[m0 + tid] = sp1[tid] + sp1[64 + tid];
                f2o[m0 + tid] = sp2[tid] + sp2[64 + tid];
            }
        }
    }
}

// ---------------- K3: layer-1 sparse attention + aggregation + elu --------
// softmax: warp w = head w.  gather: warps (hp, parity) — head pair hp=w&3,
// parity=w>>2 takes even/odd neighbors; each lane loads 4 floats (LDG.64).
__global__ void gat_agg1() {
    int n = blockIdx.x;
    __shared__ int   s_idx[MAXDEG];
    __shared__ float s_f2[NHEADS][MAXDEG];
    __shared__ float s_w [NHEADS][MAXDEG + 4];
    __shared__ float s_inv[NHEADS];
    __shared__ float s_pp[4][4][33];
    int tid = threadIdx.x;
    int deg = d_cnt[n];

    for (int j = tid; j < deg; j += 256) s_idx[j] = d_nbr[n * MAXDEG + j];
    __syncthreads();
    for (int t = tid; t < deg * NHEADS; t += 256) {
        int h = t / deg, j = t - h * deg;
        s_f2[h][j] = d_f2[h * NN + s_idx[j]];
    }
    __syncthreads();

    int w = tid >> 5, lane = tid & 31;
    {
        float f1v = d_f1[w * NN + n];
        float mx = -1e30f;
        for (int j = lane; j < deg; j += 32) mx = fmaxf(mx, leaky(f1v + s_f2[w][j]));
        #pragma unroll
        for (int off = 16; off; off >>= 1) mx = fmaxf(mx, __shfl_xor_sync(0xffffffffu, mx, off));
        float sum = 0.f;
        for (int j = lane; j < deg; j += 32) {
            float e = expf(leaky(f1v + s_f2[w][j]) - mx);
            s_w[w][j] = e;
            sum += e;
        }
        #pragma unroll
        for (int off = 16; off; off >>= 1) sum += __shfl_xor_sync(0xffffffffu, sum, off);
        if (lane == 0) s_inv[w] = 1.f / sum;
    }
    __syncthreads();

    int hp = w & 3, par = w >> 2;
    int head = 2 * hp + (lane >> 4), sub = lane & 15;
    const char* base = reinterpret_cast<const char*>(d_Whh) + (head * 32 + sub * 2) * 4;
    float a0 = 0.f, a1 = 0.f, a2 = 0.f, a3 = 0.f;
    for (int j = par; j < deg; j += 2) {
        float wt = s_w[head][j];
        uint2 u = *reinterpret_cast<const uint2*>(base + s_idx[j] * 1024);
        float2 vlo = __half22float2(*reinterpret_cast<__half2*>(&u.x));
        float2 vhi = __half22float2(*reinterpret_cast<__half2*>(&u.y));
        a0 += wt * vlo.x; a1 += wt * vlo.y;
        a2 += wt * vhi.x; a3 += wt * vhi.y;
    }
    if (par == 1) {
        s_pp[hp][0][lane] = a0; s_pp[hp][1][lane] = a1;
        s_pp[hp][2][lane] = a2; s_pp[hp][3][lane] = a3;
    }
    __syncthreads();
    if (par == 0) {
        a0 += s_pp[hp][0][lane]; a1 += s_pp[hp][1][lane];
        a2 += s_pp[hp][2][lane]; a3 += s_pp[hp][3][lane];
        float inv = s_inv[head];
        uint4 o;
        o.x = f2tf32(elu1(a0 * inv));
        o.y = f2tf32(elu1(a1 * inv));
        o.z = f2tf32(elu1(a2 * inv));
        o.w = f2tf32(elu1(a3 * inv));
        *reinterpret_cast<uint4*>(d_h1 + (size_t)n * 512 + head * 64 + sub * 4) = o;
    }
}

// ---------------- K6: layer-2 attention + aggregation (h2 only) -----------
__global__ void gat_agg2() {
    int n = blockIdx.x;
    __shared__ int   s_idx[MAXDEG];
    __shared__ float s_g2[MAXDEG];
    __shared__ float s_w [MAXDEG];
    __shared__ float s_sum;
    __shared__ float s_part[4][64];
    int tid = threadIdx.x;
    int deg = d_cnt[n];

    for (int j = tid; j < deg; j += 256) {
        int c = d_nbr[n * MAXDEG + j];
        s_idx[j] = c;
        s_g2[j]  = d_g2[c];
    }
    __syncthreads();

    if (tid < 32) {
        float g1n = d_g1[n];
        float mx = -1e30f;
        for (int j = tid; j < deg; j += 32) mx = fmaxf(mx, leaky(g1n + s_g2[j]));
        #pragma unroll
        for (int off = 16; off; off >>= 1) mx = fmaxf(mx, __shfl_xor_sync(0xffffffffu, mx, off));
        float sum = 0.f;
        for (int j = tid; j < deg; j += 32) {
            float e = expf(leaky(g1n + s_g2[j]) - mx);
            s_w[j] = e;
            sum += e;
        }
        #pragma unroll
        for (int off = 16; off; off >>= 1) sum += __shfl_xor_sync(0xffffffffu, sum, off);
        if (tid == 0) s_sum = sum;
    }
    __syncthreads();

    {
        int o = tid & 63, part = tid >> 6;
        float acc = 0.f;
        for (int j = part; j < deg; j += 4)
            acc += s_w[j] * d_Wh2[(size_t)s_idx[j] * 64 + o];
        s_part[part][o] = acc;
    }
    __syncthreads();
    if (tid < 64) {
        float h2 = (s_part[0][tid] + s_part[1][tid] + s_part[2][tid] + s_part[3][tid]) / s_sum;
        d_h2[(size_t)n * 64 + tid] = __uint_as_float(f2tf32(h2));
    }
}

// ---------------- launch ----------------------------------------------------
extern "C" void kernel_launch(void* const* d_in, const int* in_sizes, int n_in,
                              void* d_out, int out_size) {
    const float* x     = (const float*)d_in[0];
    const float* adj   = (const float*)d_in[1];
    const float* W_h   = (const float*)d_in[2];
    const float* a_h   = (const float*)d_in[3];
    const float* W_o   = (const float*)d_in[4];
    const float* a_o   = (const float*)d_in[5];
    const float* fc1_w = (const float*)d_in[6];
    const float* fc1_b = (const float*)d_in[7];
    const float* fc2_w = (const float*)d_in[8];
    const float* fc2_b = (const float*)d_in[9];
    float* out = (float*)d_out;

    void *pWhh, *pH1, *pWh2, *pH2, *pH3, *pBt1, *pBt2, *pBt3, *pBt4;
    void *pB3, *pB4, *pF1, *pF2, *pG1, *pG2;
    cudaGetSymbolAddress(&pWhh, d_Whh);
    cudaGetSymbolAddress(&pH1,  d_h1);
    cudaGetSymbolAddress(&pWh2, d_Wh2);
    cudaGetSymbolAddress(&pH2,  d_h2);
    cudaGetSymbolAddress(&pH3,  d_h3);
    cudaGetSymbolAddress(&pBt1, d_Bt1);
    cudaGetSymbolAddress(&pBt2, d_Bt2);
    cudaGetSymbolAddress(&pBt3, d_Bt3);
    cudaGetSymbolAddress(&pBt4, d_Bt4);
    cudaGetSymbolAddress(&pB3,  d_bias3);
    cudaGetSymbolAddress(&pB4,  d_bias4);
    cudaGetSymbolAddress(&pF1,  d_f1);
    cudaGetSymbolAddress(&pF2,  d_f2);
    cudaGetSymbolAddress(&pG1,  d_g1);
    cudaGetSymbolAddress(&pG2,  d_g2);

    const int MB = (NN + 63) / 64;   // 79
    const int SM_M0 = (256 + 256 + (2 * 64 + 2 * 128) * SPAD) * 4;
    const int SM_M1 = (128 + 256 + (2 * 64 + 2 * 64) * SPAD) * 4;
    const int SM_M2 = (128 + 256 + (2 * 64 + 2 * 128) * SPAD) * 4;
    const int SM_M3 = (64 + 256 + (2 * 64 + 2 * 64) * SPAD) * 4;
    cudaFuncSetAttribute(gat_mma_gemm<128, 16, 0>, cudaFuncAttributeMaxDynamicSharedMemorySize, SM_M0);
    cudaFuncSetAttribute(gat_mma_gemm<64, 16, 1>,  cudaFuncAttributeMaxDynamicSharedMemorySize, SM_M1);
    cudaFuncSetAttribute(gat_mma_gemm<128, 2, 2>,  cudaFuncAttributeMaxDynamicSharedMemorySize, SM_M2);
    cudaFuncSetAttribute(gat_mma_gemm<64, 8, 3>,   cudaFuncAttributeMaxDynamicSharedMemorySize, SM_M3);

    cudaStream_t s2;
    cudaStreamCreateWithFlags(&s2, cudaStreamNonBlocking);
    cudaEvent_t e0, e1;
    cudaEventCreateWithFlags(&e0, cudaEventDisableTiming);
    cudaEventCreateWithFlags(&e1, cudaEventDisableTiming);

    cudaEventRecord(e0, 0);
    cudaStreamWaitEvent(s2, e0, 0);
    gat_build_csr<<<NN, 256, 0, s2>>>(adj);
    cudaEventRecord(e1, s2);

    gat_prep<<<PREP_BLOCKS, 256>>>(W_h, W_o, fc1_w, fc1_b, fc2_w, fc2_b);
    gat_mma_gemm<128, 16, 0><<<dim3(MB, 4), 256, SM_M0>>>(x, 512,
        (const float*)pBt1, pWhh, NN, a_h, (float*)pF1, (float*)pF2);
    cudaStreamWaitEvent(0, e1, 0);
    gat_agg1<<<NN, 256>>>();
    gat_mma_gemm<64, 16, 1><<<dim3(MB, 1), 256, SM_M1>>>((const float*)pH1, 512,
        (const float*)pBt2, pWh2, NN, a_o, (float*)pG1, (float*)pG2);
    gat_agg2<<<NN, 256>>>();
    gat_mma_gemm<128, 2, 2><<<dim3(MB, 2), 256, SM_M2>>>((const float*)pH2, 64,
        (const float*)pBt3, pH3, NN, (const float*)pB3, nullptr, nullptr);
    gat_mma_gemm<64, 8, 3><<<dim3(MB, 1), 256, SM_M3>>>((const float*)pH3, 256,
        (const float*)pBt4, out, NN, (const float*)pB4, nullptr, nullptr);

    cudaEventDestroy(e0);
    cudaEventDestroy(e1);
    cudaStreamDestroy(s2);
}